// round 3
// baseline (speedup 1.0000x reference)
#include <cuda_runtime.h>

// ---------------------------------------------------------------------------
// PartialAttentionBlock: algebraic restructuring.
//   out[t] = 0.5 * ( softmaxN(G+Bn)·V + vn + softmaxC(G+Bc, seg==c_t)·V + vc )
// where G = q·k (one GEMM), B_c[s] = qtok_c · k_s (tiny precompute),
// row-constant logit terms cancel in softmax, counter == 2 always.
// ---------------------------------------------------------------------------

__device__ float g_tok[9 * 192];        // tokens: W_cls @ embed_table[c], c=0..8 (8 = null)
__device__ float g_B[64 * 9 * 1024];    // B[bh][c9][s] = qtok_c9 . k_{bh,s}

// ---- kernel A: class tokens --------------------------------------------------
__global__ void tok_kernel(const float* __restrict__ emb, const float* __restrict__ Wc)
{
    __shared__ float e[512];
    int c9 = blockIdx.x;
    for (int k = threadIdx.x; k < 512; k += blockDim.x) e[k] = emb[c9 * 512 + k];
    __syncthreads();
    int r = threadIdx.x;            // 0..191
    const float* w = Wc + r * 512;
    float acc = 0.f;
#pragma unroll 8
    for (int k = 0; k < 512; k++) acc = fmaf(w[k], e[k], acc);
    g_tok[c9 * 192 + r] = acc;
}

// ---- kernel B: key biases B[bh][c9][s] --------------------------------------
__global__ void bmat_kernel(const float* __restrict__ qkv)
{
    __shared__ float tq[9 * 64];
    int bh = blockIdx.x;
    for (int x = threadIdx.x; x < 576; x += blockDim.x)
        tq[x] = g_tok[(x >> 6) * 192 + (x & 63)];      // q-part of tokens
    __syncthreads();
    const float* kb = qkv + bh * 196608 + 65536;        // k plane of this bh
    for (int s = threadIdx.x; s < 1024; s += blockDim.x) {
        float acc[9];
#pragma unroll
        for (int c9 = 0; c9 < 9; c9++) acc[c9] = 0.f;
        for (int cc = 0; cc < 64; cc++) {
            float kv = kb[cc * 1024 + s];
#pragma unroll
            for (int c9 = 0; c9 < 9; c9++) acc[c9] = fmaf(tq[c9 * 64 + cc], kv, acc[c9]);
        }
#pragma unroll
        for (int c9 = 0; c9 < 9; c9++) g_B[bh * 9216 + c9 * 1024 + s] = acc[c9];
    }
}

// ---- main fused kernel -------------------------------------------------------
// grid (32 q-tiles, 64 bh), 256 threads, dynamic smem 207232 B (1 CTA/SM)
// smem layout (floats):
//   [0      , 32768) Ssm : scores / combined weights, swizzled (s*32 + (i ^ (s&31)))
//   [32768  , 34816) Qs  : Q tile [64][32] (c-major)
//   [34816  , 51200) KV  : K tile [64][256]  ->  V^T tile swizzled  ->  partials
//   [51200  , 51776) tokv: v-part of tokens [9][64]
//   [51776  , 51808) segq: per-query class (int)
__global__ void __launch_bounds__(256, 1)
attn_kernel(const float* __restrict__ qkv, const int* __restrict__ mask,
            float* __restrict__ out)
{
    extern __shared__ float sm[];
    float* Ssm  = sm;
    float* Qs   = sm + 32768;
    float* KV   = sm + 34816;
    float* tokv = sm + 51200;
    int*   segq = (int*)(sm + 51776);

    const int tid = threadIdx.x;
    const int bh  = blockIdx.y;
    const int t0  = blockIdx.x * 32;
    const int b   = bh >> 3;
    const float* qb = qkv + bh * 196608;

    // preload Q tile (c-major [64][32]), token v-parts, query segments
#pragma unroll
    for (int r = 0; r < 8; r++) {
        int f = tid + 256 * r;
        int c = f >> 5, i = f & 31;
        Qs[c * 32 + i] = qb[c * 1024 + t0 + i];
    }
    for (int x = tid; x < 576; x += 256)
        tokv[x] = g_tok[(x >> 6) * 192 + 128 + (x & 63)];
    if (tid < 32) segq[tid] = mask[b * 1024 + t0 + tid];

    // ================= phase 1: G = Q^T K =================
    const int qg = tid >> 5, sg = tid & 31;      // warp = fixed qg
    const float* kbase = qb + 65536;
    for (int tile = 0; tile < 4; tile++) {
        const int s0 = tile * 256;
        __syncthreads();
#pragma unroll
        for (int r = 0; r < 16; r++) {           // load K tile [64][256]
            int f = tid + 256 * r;
            int c = f >> 6, j4 = f & 63;
            float4 kv = *(const float4*)(kbase + c * 1024 + s0 + 4 * j4);
            *(float4*)(KV + c * 256 + 4 * j4) = kv;
        }
        __syncthreads();
        float acc[4][8];
#pragma unroll
        for (int a = 0; a < 4; a++)
#pragma unroll
            for (int bb = 0; bb < 8; bb++) acc[a][bb] = 0.f;
#pragma unroll 4
        for (int c = 0; c < 64; c++) {
            float4 q4  = *(const float4*)(Qs + c * 32 + 4 * qg);        // broadcast
            float4 ka  = *(const float4*)(KV + c * 256 + 4 * sg);       // contiguous
            float4 kb4 = *(const float4*)(KV + c * 256 + 128 + 4 * sg); // contiguous
            float qv[4] = {q4.x, q4.y, q4.z, q4.w};
            float kv[8] = {ka.x, ka.y, ka.z, ka.w, kb4.x, kb4.y, kb4.z, kb4.w};
#pragma unroll
            for (int a = 0; a < 4; a++)
#pragma unroll
                for (int bb = 0; bb < 8; bb++)
                    acc[a][bb] = fmaf(qv[a], kv[bb], acc[a][bb]);
        }
#pragma unroll
        for (int a = 0; a < 4; a++) {
            int i = 4 * qg + a;
#pragma unroll
            for (int bb = 0; bb < 8; bb++) {
                int s = s0 + ((bb < 4) ? (4 * sg + bb) : (128 + 4 * sg + bb - 4));
                Ssm[s * 32 + (i ^ (s & 31))] = acc[a][bb];
            }
        }
    }
    __syncthreads();

    // ================= phase 2: two softmaxes -> combined weights =================
    {
        const int warp = tid >> 5, lane = tid & 31;
        const float* Bn = g_B + bh * 9216 + 8192;   // null token biases
        const float* Bb = g_B + bh * 9216;
        const int* segs = mask + b * 1024;
        const float SC2 = 0.125f;                    // scale^2 = ch^-0.5
        for (int rr = 0; rr < 4; rr++) {
            int i = warp * 4 + rr;
            int ci = segq[i];
            const float* Bc = Bb + ci * 1024;
            float mN = -1e30f, mC = -1e30f;
            for (int k = 0; k < 32; k++) {
                int s = lane + 32 * k;
                float G = Ssm[s * 32 + (i ^ (s & 31))];
                mN = fmaxf(mN, SC2 * (G + Bn[s]));
                if (segs[s] == ci) mC = fmaxf(mC, SC2 * (G + Bc[s]));
            }
#pragma unroll
            for (int o = 16; o > 0; o >>= 1) {
                mN = fmaxf(mN, __shfl_xor_sync(0xffffffffu, mN, o));
                mC = fmaxf(mC, __shfl_xor_sync(0xffffffffu, mC, o));
            }
            float sN = 0.f, sC = 0.f;
            for (int k = 0; k < 32; k++) {
                int s = lane + 32 * k;
                float G = Ssm[s * 32 + (i ^ (s & 31))];
                sN += __expf(SC2 * (G + Bn[s]) - mN);
                if (segs[s] == ci) sC += __expf(SC2 * (G + Bc[s]) - mC);
            }
#pragma unroll
            for (int o = 16; o > 0; o >>= 1) {
                sN += __shfl_xor_sync(0xffffffffu, sN, o);
                sC += __shfl_xor_sync(0xffffffffu, sC, o);
            }
            float rN = 1.f / sN, rC = 1.f / sC;
            for (int k = 0; k < 32; k++) {
                int s = lane + 32 * k;
                int idx = s * 32 + (i ^ (s & 31));
                float G = Ssm[idx];
                float w = __expf(SC2 * (G + Bn[s]) - mN) * rN;
                if (segs[s] == ci) w += __expf(SC2 * (G + Bc[s]) - mC) * rC;
                Ssm[idx] = w;                        // combined weight
            }
        }
    }
    __syncthreads();

    // ================= phase 3: out = W . V (split-s x4) =================
    {
        const int grp = tid >> 6;             // s-quarter within tile
        const int qg3 = (tid >> 3) & 7;
        const int cg  = tid & 7;
        const float* vbase = qb + 131072;
        float acc[4][8];
#pragma unroll
        for (int m = 0; m < 4; m++)
#pragma unroll
            for (int n = 0; n < 8; n++) acc[m][n] = 0.f;

        for (int tile = 0; tile < 4; tile++) {
            const int s0 = tile * 256;
            __syncthreads();
#pragma unroll
            for (int r = 0; r < 16; r++) {    // load V tile transposed+swizzled
                int f = tid + 256 * r;
                int c = f >> 6, j4 = f & 63;
                float4 vv = *(const float4*)(vbase + c * 1024 + s0 + 4 * j4);
                int cs = c ^ (j4 & 31);
                KV[(4 * j4 + 0) * 64 + cs] = vv.x;
                KV[(4 * j4 + 1) * 64 + cs] = vv.y;
                KV[(4 * j4 + 2) * 64 + cs] = vv.z;
                KV[(4 * j4 + 3) * 64 + cs] = vv.w;
            }
            __syncthreads();
#pragma unroll 2
            for (int jj = 0; jj < 64; jj++) {
                int j = grp * 64 + jj;
                int s = s0 + j;
                int sk = s & 31;
                int vk = (j >> 2) & 31;
                float wv[4], vv[8];
#pragma unroll
                for (int m = 0; m < 4; m++) wv[m] = Ssm[s * 32 + ((4 * qg3 + m) ^ sk)];
#pragma unroll
                for (int n = 0; n < 8; n++) vv[n] = KV[j * 64 + ((8 * cg + n) ^ vk)];
#pragma unroll
                for (int m = 0; m < 4; m++)
#pragma unroll
                    for (int n = 0; n < 8; n++)
                        acc[m][n] = fmaf(wv[m], vv[n], acc[m][n]);
            }
        }
        __syncthreads();
        // partials into KV: [grp][c][i]
#pragma unroll
        for (int m = 0; m < 4; m++)
#pragma unroll
            for (int n = 0; n < 8; n++)
                KV[grp * 2048 + (8 * cg + n) * 32 + (4 * qg3 + m)] = acc[m][n];
    }
    __syncthreads();

    // ================= epilogue: reduce, add token v-parts, /2, store ==========
    {
        int i = tid & 31, cb = tid >> 5;
        int ci = segq[i];
#pragma unroll
        for (int rr = 0; rr < 8; rr++) {
            int c = cb * 8 + rr;
            float sum = KV[c * 32 + i] + KV[2048 + c * 32 + i]
                      + KV[4096 + c * 32 + i] + KV[6144 + c * 32 + i];
            float val = 0.5f * (sum + tokv[512 + c] + tokv[ci * 64 + c]);
            // output flat index: c*(bH*T) + bh*T + t
            out[c * 65536 + bh * 1024 + t0 + i] = val;
        }
    }
}

// ---------------------------------------------------------------------------
extern "C" void kernel_launch(void* const* d_in, const int* in_sizes, int n_in,
                              void* d_out, int out_size)
{
    const float* qkv  = (const float*)d_in[0];
    const int*   mask = (const int*)  d_in[1];
    const float* emb  = (const float*)d_in[2];
    const float* Wc   = (const float*)d_in[3];
    float* out = (float*)d_out;

    tok_kernel<<<9, 192>>>(emb, Wc);
    bmat_kernel<<<64, 256>>>(qkv);

    const int SMEM = 51808 * 4;   // 207232 B
    cudaFuncSetAttribute(attn_kernel, cudaFuncAttributeMaxDynamicSharedMemorySize, SMEM);
    attn_kernel<<<dim3(32, 64), 256, SMEM>>>(qkv, mask, out);
}

// round 5
// speedup vs baseline: 7.4916x; 7.4916x over previous
#include <cuda_runtime.h>
#include <cuda_fp16.h>
#include <cstdint>

// ============================================================================
// out[t] = 0.5*( softmaxN(G+Bn)V + vn + softmaxC(G+Bc; seg==c_t)V + vc )
// G = Q.K^T via mma.sync HMMA (fp16 hi/lo 3-split). Unnormalized exp2 weights
// repacked in-register as PV A-fragments; two fp32 accumulators; counter==2.
// NOTE: tcgen05 is NOT available (harness compiles PTX for compute_103, and
// tcgen05 requires the sm_103a arch-specific target) -> HMMA path.
// ============================================================================

#define SCL 0.18033688011112042f   // 0.125 * log2(e)

__device__ float g_tok[9 * 192];
__device__ float g_R[64 * 1024 * 8];   // [bh][s][c] masked exp2(SCL*(Bc-Bn))
__device__ float g_bn2[64 * 1024];     // [bh][s] = SCL*Bn

__device__ __forceinline__ uint32_t smem_u32(const void* p) {
    uint32_t a;
    asm("{ .reg .u64 t; cvta.to.shared.u64 t, %1; cvt.u32.u64 %0, t; }" : "=r"(a) : "l"(p));
    return a;
}
__device__ __forceinline__ float ex2f(float x) {
    float y; asm("ex2.approx.f32 %0, %1;" : "=f"(y) : "f"(x)); return y;
}
__device__ __forceinline__ uint32_t packh2(float lo, float hi) {
    uint32_t r; asm("cvt.rn.f16x2.f32 %0, %1, %2;" : "=r"(r) : "f"(hi), "f"(lo)); return r;
}
__device__ __forceinline__ uint32_t SW(uint32_t off) {      // 256B-pitch swizzle
    return off ^ ((off >> 4) & 0x70);
}
__device__ __forceinline__ void ldsm4t(uint32_t* r, uint32_t addr) {
    asm volatile("ldmatrix.sync.aligned.m8n8.x4.trans.shared.b16 {%0,%1,%2,%3}, [%4];"
        : "=r"(r[0]), "=r"(r[1]), "=r"(r[2]), "=r"(r[3]) : "r"(addr));
}
__device__ __forceinline__ void ldsm4(uint32_t* r, uint32_t addr) {
    asm volatile("ldmatrix.sync.aligned.m8n8.x4.shared.b16 {%0,%1,%2,%3}, [%4];"
        : "=r"(r[0]), "=r"(r[1]), "=r"(r[2]), "=r"(r[3]) : "r"(addr));
}
__device__ __forceinline__ void hmma(float* c, const uint32_t* a, uint32_t b0, uint32_t b1) {
    asm volatile("mma.sync.aligned.m16n8k16.row.col.f32.f16.f16.f32 "
        "{%0,%1,%2,%3},{%4,%5,%6,%7},{%8,%9},{%0,%1,%2,%3};"
        : "+f"(c[0]), "+f"(c[1]), "+f"(c[2]), "+f"(c[3])
        : "r"(a[0]), "r"(a[1]), "r"(a[2]), "r"(a[3]), "r"(b0), "r"(b1));
}

// ---------------- aux A: class tokens (coalesced, warp-per-row) ----------------
__global__ void tok_kernel(const float* __restrict__ emb, const float* __restrict__ Wc)
{
    __shared__ float e[512];
    int c9 = blockIdx.x;
    for (int k = threadIdx.x; k < 512; k += 256) e[k] = emb[c9 * 512 + k];
    __syncthreads();
    int w = threadIdx.x >> 5, l = threadIdx.x & 31;
    for (int rr = 0; rr < 24; rr++) {
        int r = w * 24 + rr;
        const float* wr = Wc + r * 512;
        float acc = 0.f;
#pragma unroll
        for (int k = 0; k < 16; k++) acc = fmaf(wr[l + 32 * k], e[l + 32 * k], acc);
#pragma unroll
        for (int o = 16; o > 0; o >>= 1) acc += __shfl_xor_sync(0xffffffffu, acc, o);
        if (l == 0) g_tok[c9 * 192 + r] = acc;
    }
}

// ---------------- aux B: bn2 + masked exp2 ratio table ----------------
__global__ void bmat_kernel(const float* __restrict__ qkv, const int* __restrict__ mask)
{
    __shared__ float tq[9 * 64];
    int bh = blockIdx.x, b = bh >> 3;
    for (int x = threadIdx.x; x < 576; x += 256) tq[x] = g_tok[(x >> 6) * 192 + (x & 63)];
    __syncthreads();
    const float* kb = qkv + bh * 196608 + 65536;
    for (int s = threadIdx.x; s < 1024; s += 256) {
        float acc[9];
#pragma unroll
        for (int c = 0; c < 9; c++) acc[c] = 0.f;
        for (int c = 0; c < 64; c++) {
            float kv = kb[c * 1024 + s];
#pragma unroll
            for (int c9 = 0; c9 < 9; c9++) acc[c9] = fmaf(tq[c9 * 64 + c], kv, acc[c9]);
        }
        float bn = acc[8];
        g_bn2[bh * 1024 + s] = SCL * bn;
        int sg = mask[b * 1024 + s];
        float r[8];
#pragma unroll
        for (int c = 0; c < 8; c++) r[c] = (sg == c) ? ex2f(SCL * (acc[c] - bn)) : 0.f;
        float4* dst = (float4*)(g_R + bh * 8192 + s * 8);
        dst[0] = make_float4(r[0], r[1], r[2], r[3]);
        dst[1] = make_float4(r[4], r[5], r[6], r[7]);
    }
}

// ---------------- main kernel ----------------
// smem byte offsets; tiles are [64ch][128elem] fp16, pitch 256B, SW-swizzled
#define OFF_QHI   0
#define OFF_QLO   16384
#define OFF_KHI   32768
#define OFF_KLO   49152
#define OFF_V     65536
#define OFF_OUT   32768          /* overlay after chunks: 64 x 132 f32 = 33792B */
#define OFF_R     81920
#define OFF_BN2   114688
#define OFF_TOKV  118784         /* [9][68] f32 */
#define OFF_SEGQ  121344
#define SMEM_DYN  122368

__global__ void __launch_bounds__(256, 1)
attn_kernel(const float* __restrict__ qkv, const int* __restrict__ mask,
            float* __restrict__ out)
{
    extern __shared__ __align__(16) char smc[];
    const uint32_t sb = smem_u32(smc);

    const int tid = threadIdx.x;
    const int w = tid >> 5, lane = tid & 31;
    const int g = lane >> 2, tg = lane & 3;
    const int bh = blockIdx.y;
    const int t0 = blockIdx.x * 128;
    const int b = bh >> 3;
    const float* qplane = qkv + bh * 196608;
    const float* kplane = qplane + 65536;
    const float* vplane = qplane + 131072;

    // ---- prologue: Q tile (hi/lo), R, bn2, tokv, segq ----
#pragma unroll
    for (int rep = 0; rep < 8; rep++) {          // Q [64ch][128t]
        int idx = rep * 256 + tid;
        int c = idx >> 5, t4 = (idx & 31) * 4;
        float4 v = *(const float4*)(qplane + c * 1024 + t0 + t4);
        uint32_t h0 = packh2(v.x, v.y), h1 = packh2(v.z, v.w);
        __half2 a0 = *reinterpret_cast<__half2*>(&h0);
        __half2 a1 = *reinterpret_cast<__half2*>(&h1);
        uint32_t l0 = packh2(v.x - __low2float(a0), v.y - __high2float(a0));
        uint32_t l1 = packh2(v.z - __low2float(a1), v.w - __high2float(a1));
        uint32_t sw = SW((uint32_t)c * 256 + t4 * 2);
        *(uint2*)(smc + OFF_QHI + sw) = make_uint2(h0, h1);
        *(uint2*)(smc + OFF_QLO + sw) = make_uint2(l0, l1);
    }
    {
        const float4* Rg = (const float4*)(g_R + bh * 8192);
        float4* Rs = (float4*)(smc + OFF_R);
#pragma unroll
        for (int rep = 0; rep < 8; rep++) Rs[tid + rep * 256] = Rg[tid + rep * 256];
        ((float4*)(smc + OFF_BN2))[tid] = ((const float4*)(g_bn2 + bh * 1024))[tid];
        float* tvs = (float*)(smc + OFF_TOKV);
        for (int x = tid; x < 576; x += 256)
            tvs[(x >> 6) * 68 + (x & 63)] = g_tok[(x >> 6) * 192 + 128 + (x & 63)];
        if (tid < 128) ((int*)(smc + OFF_SEGQ))[tid] = mask[b * 1024 + t0 + tid];
    }
    __syncthreads();

    const int m0w = w * 16;
    const int ci_lo = ((const int*)(smc + OFF_SEGQ))[m0w + g];
    const int ci_hi = ((const int*)(smc + OFF_SEGQ))[m0w + g + 8];
    const float* Rsm = (const float*)(smc + OFF_R);
    const float* bn2sm = (const float*)(smc + OFF_BN2);

    // ---- persistent Q A-fragments (hi & lo), 4 k-steps ----
    uint32_t qh[4][4], ql[4][4];
    {
        int kkA = (lane & 7) + ((lane >> 4) << 3);
        int mmA = m0w + ((lane >> 3) & 1) * 8;
#pragma unroll
        for (int k = 0; k < 4; k++) {
            uint32_t sw = SW((uint32_t)(16 * k + kkA) * 256 + mmA * 2);
            ldsm4t(qh[k], sb + OFF_QHI + sw);
            ldsm4t(ql[k], sb + OFF_QLO + sw);
        }
    }

    float accN[32], accC[32];
#pragma unroll
    for (int i = 0; i < 32; i++) { accN[i] = 0.f; accC[i] = 0.f; }
    float sNlo = 0.f, sNhi = 0.f, sClo = 0.f, sChi = 0.f;

    const int kkB = lane & 15, nnB8 = (lane >> 4) * 8;                 // K frag addr parts
    const int nnV = (lane >> 4) * 8 + (lane & 7), kkV8 = ((lane >> 3) & 1) * 8;  // V parts

    for (int chk = 0; chk < 8; chk++) {
        const int s0 = chk * 128;
        __syncthreads();
        // load K chunk (hi/lo) + V chunk, fp16, gmem layout [64ch][128s]
#pragma unroll
        for (int rep = 0; rep < 8; rep++) {
            int idx = rep * 256 + tid;
            int c = idx >> 5, s4 = (idx & 31) * 4;
            float4 v = *(const float4*)(kplane + c * 1024 + s0 + s4);
            uint32_t h0 = packh2(v.x, v.y), h1 = packh2(v.z, v.w);
            __half2 a0 = *reinterpret_cast<__half2*>(&h0);
            __half2 a1 = *reinterpret_cast<__half2*>(&h1);
            uint32_t l0 = packh2(v.x - __low2float(a0), v.y - __high2float(a0));
            uint32_t l1 = packh2(v.z - __low2float(a1), v.w - __high2float(a1));
            uint32_t sw = SW((uint32_t)c * 256 + s4 * 2);
            *(uint2*)(smc + OFF_KHI + sw) = make_uint2(h0, h1);
            *(uint2*)(smc + OFF_KLO + sw) = make_uint2(l0, l1);
            float4 vv = *(const float4*)(vplane + c * 1024 + s0 + s4);
            *(uint2*)(smc + OFF_V + sw) = make_uint2(packh2(vv.x, vv.y), packh2(vv.z, vv.w));
        }
        __syncthreads();

#pragma unroll
        for (int half = 0; half < 2; half++) {
            const int hb = half * 64;
            uint32_t WN0[8], WN1[8], WC0[8], WC1[8];
#pragma unroll
            for (int ntp = 0; ntp < 4; ntp++) {
                float S[8];
#pragma unroll
                for (int i = 0; i < 8; i++) S[i] = 0.f;
#pragma unroll
                for (int k = 0; k < 4; k++) {
                    uint32_t bh4[4], bl4[4];
                    uint32_t offK = SW((uint32_t)(16 * k + kkB) * 256 + (hb + ntp * 16 + nnB8) * 2);
                    ldsm4t(bh4, sb + OFF_KHI + offK);
                    ldsm4t(bl4, sb + OFF_KLO + offK);
                    hmma(S, qh[k], bh4[0], bh4[1]);
                    hmma(S, qh[k], bl4[0], bl4[1]);
                    hmma(S, ql[k], bh4[0], bh4[1]);
                    hmma(S + 4, qh[k], bh4[2], bh4[3]);
                    hmma(S + 4, qh[k], bl4[2], bl4[3]);
                    hmma(S + 4, ql[k], bh4[2], bh4[3]);
                }
#pragma unroll
                for (int t = 0; t < 2; t++) {
                    const int nt = 2 * ntp + t;
                    const int sA = s0 + hb + nt * 8 + 2 * tg;
                    float b2A = bn2sm[sA], b2B = bn2sm[sA + 1];
                    float e0 = ex2f(fmaf(S[4 * t + 0], SCL, b2A));
                    float e1 = ex2f(fmaf(S[4 * t + 1], SCL, b2B));
                    float e2 = ex2f(fmaf(S[4 * t + 2], SCL, b2A));
                    float e3 = ex2f(fmaf(S[4 * t + 3], SCL, b2B));
                    sNlo += e0 + e1; sNhi += e2 + e3;
                    WN0[nt] = packh2(e0, e1);
                    WN1[nt] = packh2(e2, e3);
                    float c0 = e0 * Rsm[sA * 8 + ci_lo];
                    float c1 = e1 * Rsm[(sA + 1) * 8 + ci_lo];
                    float c2 = e2 * Rsm[sA * 8 + ci_hi];
                    float c3 = e3 * Rsm[(sA + 1) * 8 + ci_hi];
                    sClo += c0 + c1; sChi += c2 + c3;
                    WC0[nt] = packh2(c0, c1);
                    WC1[nt] = packh2(c2, c3);
                }
            }
            // PV: acc += W * V
#pragma unroll
            for (int j = 0; j < 4; j++) {
                uint32_t aN[4] = { WN0[2 * j], WN1[2 * j], WN0[2 * j + 1], WN1[2 * j + 1] };
                uint32_t aC[4] = { WC0[2 * j], WC1[2 * j], WC0[2 * j + 1], WC1[2 * j + 1] };
                const int k0v = hb + j * 16;
#pragma unroll
                for (int np = 0; np < 4; np++) {
                    uint32_t bv[4];
                    ldsm4(bv, sb + OFF_V + SW((uint32_t)(np * 16 + nnV) * 256 + (k0v + kkV8) * 2));
                    hmma(accN + (2 * np) * 4, aN, bv[0], bv[1]);
                    hmma(accC + (2 * np) * 4, aC, bv[0], bv[1]);
                    hmma(accN + (2 * np + 1) * 4, aN, bv[2], bv[3]);
                    hmma(accC + (2 * np + 1) * 4, aC, bv[2], bv[3]);
                }
            }
        }
    }

    // ---- row-sum reduce across the 4 lanes sharing a row ----
#pragma unroll
    for (int o = 1; o < 4; o <<= 1) {
        sNlo += __shfl_xor_sync(0xffffffffu, sNlo, o);
        sNhi += __shfl_xor_sync(0xffffffffu, sNhi, o);
        sClo += __shfl_xor_sync(0xffffffffu, sClo, o);
        sChi += __shfl_xor_sync(0xffffffffu, sChi, o);
    }
    const float rsNlo = 0.5f / sNlo, rsNhi = 0.5f / sNhi;
    const float rsClo = 0.5f / sClo, rsChi = 0.5f / sChi;

    __syncthreads();   // all warps done reading K/V smem before OUT overlay

    // ---- stage normalized output to smem [64c][q] pitch 132 f32 ----
    {
        float* so = (float*)(smc + OFF_OUT);
        const float* tv8 = (const float*)(smc + OFF_TOKV) + 8 * 68;
        const float* tvl = (const float*)(smc + OFF_TOKV) + ci_lo * 68;
        const float* tvh = (const float*)(smc + OFF_TOKV) + ci_hi * 68;
#pragma unroll
        for (int nt = 0; nt < 8; nt++) {
            int c0 = nt * 8 + 2 * tg;
            so[c0 * 132 + m0w + g] =
                accN[nt * 4 + 0] * rsNlo + accC[nt * 4 + 0] * rsClo + 0.5f * (tv8[c0] + tvl[c0]);
            so[(c0 + 1) * 132 + m0w + g] =
                accN[nt * 4 + 1] * rsNlo + accC[nt * 4 + 1] * rsClo + 0.5f * (tv8[c0 + 1] + tvl[c0 + 1]);
            so[c0 * 132 + m0w + g + 8] =
                accN[nt * 4 + 2] * rsNhi + accC[nt * 4 + 2] * rsChi + 0.5f * (tv8[c0] + tvh[c0]);
            so[(c0 + 1) * 132 + m0w + g + 8] =
                accN[nt * 4 + 3] * rsNhi + accC[nt * 4 + 3] * rsChi + 0.5f * (tv8[c0 + 1] + tvh[c0 + 1]);
        }
    }
    __syncthreads();

    // ---- coalesced copy-out: out[c*65536 + bh*1024 + t] ----
    {
        const float* so = (const float*)(smc + OFF_OUT);
#pragma unroll
        for (int rep = 0; rep < 8; rep++) {
            int idx = rep * 256 + tid;
            int c = idx >> 5, q4 = (idx & 31) * 4;
            float4 v = *(const float4*)(so + c * 132 + q4);
            *(float4*)(out + c * 65536 + bh * 1024 + t0 + q4) = v;
        }
    }
}

// ---------------------------------------------------------------------------
extern "C" void kernel_launch(void* const* d_in, const int* in_sizes, int n_in,
                              void* d_out, int out_size)
{
    const float* qkv  = (const float*)d_in[0];
    const int*   mask = (const int*)  d_in[1];
    const float* emb  = (const float*)d_in[2];
    const float* Wc   = (const float*)d_in[3];
    float* out = (float*)d_out;

    tok_kernel<<<9, 256>>>(emb, Wc);
    bmat_kernel<<<64, 256>>>(qkv, mask);
    cudaFuncSetAttribute(attn_kernel, cudaFuncAttributeMaxDynamicSharedMemorySize, SMEM_DYN);
    attn_kernel<<<dim3(8, 64), 256, SMEM_DYN>>>(qkv, mask, out);
}

// round 6
// speedup vs baseline: 8.6364x; 1.1528x over previous
#include <cuda_runtime.h>
#include <cuda_fp16.h>
#include <cstdint>

// ============================================================================
// out[t] = 0.5*( softmaxN(G+Bn)V + vn + softmaxC(G+Bc; seg==c_t)V + vc )
// G = Q.K^T via mma.sync HMMA (fp16 hi/lo 3-split). Unnormalized exp2 weights
// repacked in-register as PV A-fragments; two fp32 accumulators; counter==2.
// R6: preconverted fp16 tiles in gmem (swizzled smem image) + cp.async
// double-buffered pipeline; parallelized aux kernels.
// ============================================================================

#define SCL 0.18033688011112042f   // 0.125 * log2(e)

__device__ float g_tok[9 * 192];
__device__ float g_R[64 * 1024 * 8];   // [bh][s][c] masked exp2(SCL*(Bc-Bn))
__device__ float g_bn2[64 * 1024];     // [bh][s] = SCL*Bn
// preconverted tiles: 16KB per tile, byte-image of the smem tile (swizzled)
__device__ __align__(16) unsigned char g_hi[64 * 2 * 8 * 16384];  // [bh][q/k][tile]
__device__ __align__(16) unsigned char g_lo[64 * 2 * 8 * 16384];
__device__ __align__(16) unsigned char g_vh[64 * 8 * 16384];      // [bh][tile]

__device__ __forceinline__ uint32_t smem_u32(const void* p) {
    uint32_t a;
    asm("{ .reg .u64 t; cvta.to.shared.u64 t, %1; cvt.u32.u64 %0, t; }" : "=r"(a) : "l"(p));
    return a;
}
__device__ __forceinline__ float ex2f(float x) {
    float y; asm("ex2.approx.f32 %0, %1;" : "=f"(y) : "f"(x)); return y;
}
__device__ __forceinline__ uint32_t packh2(float lo, float hi) {
    uint32_t r; asm("cvt.rn.f16x2.f32 %0, %1, %2;" : "=r"(r) : "f"(hi), "f"(lo)); return r;
}
__device__ __forceinline__ uint32_t SW(uint32_t off) {      // 256B-pitch swizzle
    return off ^ ((off >> 4) & 0x70);
}
__device__ __forceinline__ void ldsm4t(uint32_t* r, uint32_t addr) {
    asm volatile("ldmatrix.sync.aligned.m8n8.x4.trans.shared.b16 {%0,%1,%2,%3}, [%4];"
        : "=r"(r[0]), "=r"(r[1]), "=r"(r[2]), "=r"(r[3]) : "r"(addr));
}
__device__ __forceinline__ void ldsm4(uint32_t* r, uint32_t addr) {
    asm volatile("ldmatrix.sync.aligned.m8n8.x4.shared.b16 {%0,%1,%2,%3}, [%4];"
        : "=r"(r[0]), "=r"(r[1]), "=r"(r[2]), "=r"(r[3]) : "r"(addr));
}
__device__ __forceinline__ void hmma(float* c, const uint32_t* a, uint32_t b0, uint32_t b1) {
    asm volatile("mma.sync.aligned.m16n8k16.row.col.f32.f16.f16.f32 "
        "{%0,%1,%2,%3},{%4,%5,%6,%7},{%8,%9},{%0,%1,%2,%3};"
        : "+f"(c[0]), "+f"(c[1]), "+f"(c[2]), "+f"(c[3])
        : "r"(a[0]), "r"(a[1]), "r"(a[2]), "r"(a[3]), "r"(b0), "r"(b1));
}
#define CPA_COMMIT() asm volatile("cp.async.commit_group;" ::: "memory")
__device__ __forceinline__ void cpa16(uint32_t dst, const void* src) {
    asm volatile("cp.async.cg.shared.global [%0], [%1], 16;" :: "r"(dst), "l"(src) : "memory");
}
__device__ __forceinline__ void cpa_tile(uint32_t dst, const unsigned char* src, int tid) {
#pragma unroll
    for (int rep = 0; rep < 4; rep++) {
        uint32_t o = (uint32_t)(rep * 256 + tid) * 16;
        cpa16(dst + o, src + o);
    }
}

// ---------------- preconvert: qkv f32 -> swizzled fp16 tile images ----------------
__global__ void preconv_kernel(const float* __restrict__ qkv)
{
    int idx = blockIdx.x * 256 + threadIdx.x;          // 64*192*256 total
    int t4 = (idx & 255) * 4;
    int ch = (idx >> 8) % 192;
    int bh = idx / (256 * 192);
    float4 v = *(const float4*)(qkv + (size_t)bh * 196608 + ch * 1024 + t4);
    uint32_t h0 = packh2(v.x, v.y), h1 = packh2(v.z, v.w);
    int tile = t4 >> 7, s = t4 & 127;
    if (ch < 128) {
        int p = ch >> 6, c = ch & 63;
        __half2 a0 = *reinterpret_cast<__half2*>(&h0);
        __half2 a1 = *reinterpret_cast<__half2*>(&h1);
        uint32_t l0 = packh2(v.x - __low2float(a0), v.y - __high2float(a0));
        uint32_t l1 = packh2(v.z - __low2float(a1), v.w - __high2float(a1));
        uint32_t off = SW((uint32_t)c * 256 + s * 2);
        size_t base = ((size_t)(bh * 2 + p) * 8 + tile) * 16384;
        *(uint2*)(g_hi + base + off) = make_uint2(h0, h1);
        *(uint2*)(g_lo + base + off) = make_uint2(l0, l1);
    } else {
        int c = ch - 128;
        uint32_t off = SW((uint32_t)c * 256 + s * 2);
        size_t base = ((size_t)bh * 8 + tile) * 16384;
        *(uint2*)(g_vh + base + off) = make_uint2(h0, h1);
    }
}

// ---------------- aux A: class tokens (grid 9 x 6, 4 rows/warp) ----------------
__global__ void tok_kernel(const float* __restrict__ emb, const float* __restrict__ Wc)
{
    __shared__ float e[512];
    int c9 = blockIdx.x;
    for (int k = threadIdx.x; k < 512; k += 256) e[k] = emb[c9 * 512 + k];
    __syncthreads();
    int w = threadIdx.x >> 5, l = threadIdx.x & 31;
#pragma unroll
    for (int rr = 0; rr < 4; rr++) {
        int r = blockIdx.y * 32 + w * 4 + rr;
        const float* wr = Wc + r * 512;
        float acc = 0.f;
#pragma unroll
        for (int k = 0; k < 16; k++) acc = fmaf(wr[l + 32 * k], e[l + 32 * k], acc);
#pragma unroll
        for (int o = 16; o > 0; o >>= 1) acc += __shfl_xor_sync(0xffffffffu, acc, o);
        if (l == 0) g_tok[c9 * 192 + r] = acc;
    }
}

// ---------------- aux B: bn2 + masked exp2 ratio table (grid 64 x 4) ----------------
__global__ void bmat_kernel(const float* __restrict__ qkv, const int* __restrict__ mask)
{
    __shared__ float tq[9 * 64];
    int bh = blockIdx.x, b = bh >> 3;
    for (int x = threadIdx.x; x < 576; x += 256) tq[x] = g_tok[(x >> 6) * 192 + (x & 63)];
    __syncthreads();
    const float* kb = qkv + bh * 196608 + 65536;
    int s = blockIdx.y * 256 + threadIdx.x;
    float acc[9];
#pragma unroll
    for (int c = 0; c < 9; c++) acc[c] = 0.f;
#pragma unroll 4
    for (int c = 0; c < 64; c++) {
        float kv = kb[c * 1024 + s];
#pragma unroll
        for (int c9 = 0; c9 < 9; c9++) acc[c9] = fmaf(tq[c9 * 64 + c], kv, acc[c9]);
    }
    float bn = acc[8];
    g_bn2[bh * 1024 + s] = SCL * bn;
    int sg = mask[b * 1024 + s];
    float r[8];
#pragma unroll
    for (int c = 0; c < 8; c++) r[c] = (sg == c) ? ex2f(SCL * (acc[c] - bn)) : 0.f;
    float4* dst = (float4*)(g_R + bh * 8192 + s * 8);
    dst[0] = make_float4(r[0], r[1], r[2], r[3]);
    dst[1] = make_float4(r[4], r[5], r[6], r[7]);
}

// ---------------- main kernel ----------------
#define OFF_QHI   0u
#define OFF_QLO   16384u
#define OFF_BUF   32768u          /* 2 x (KHI 16K, KLO 16K, V 16K) = 96KB */
#define OFF_R     131072u
#define OFF_BN2   163840u
#define OFF_TOKV  167936u         /* [9][68] f32 */
#define OFF_SEGQ  170384u
#define OFF_OUT   32768u          /* overlay on buffers after mainloop */
#define SMEM_DYN  171008

__global__ void __launch_bounds__(256, 1)
attn_kernel(const float* __restrict__ qkv, const int* __restrict__ mask,
            float* __restrict__ out)
{
    extern __shared__ __align__(16) char smc[];
    const uint32_t sb = smem_u32(smc);

    const int tid = threadIdx.x;
    const int w = tid >> 5, lane = tid & 31;
    const int g = lane >> 2, tg = lane & 3;
    const int bh = blockIdx.y;
    const int qt = blockIdx.x;
    const int t0 = qt * 128;
    const int b = bh >> 3;

    const unsigned char* qhi_g = g_hi + ((size_t)(bh * 2) * 8 + qt) * 16384;
    const unsigned char* qlo_g = g_lo + ((size_t)(bh * 2) * 8 + qt) * 16384;
    const unsigned char* khi_g = g_hi + ((size_t)(bh * 2 + 1) * 8) * 16384;
    const unsigned char* klo_g = g_lo + ((size_t)(bh * 2 + 1) * 8) * 16384;
    const unsigned char* v_g   = g_vh + ((size_t)bh * 8) * 16384;

    // ---- prologue: group0 = Q hi/lo + R + bn2 ; group1 = chunk 0 ----
    cpa_tile(sb + OFF_QHI, qhi_g, tid);
    cpa_tile(sb + OFF_QLO, qlo_g, tid);
    {
        const unsigned char* Rg = (const unsigned char*)(g_R + bh * 8192);
#pragma unroll
        for (int rep = 0; rep < 8; rep++) {
            uint32_t o = (uint32_t)(rep * 256 + tid) * 16;
            cpa16(sb + OFF_R + o, Rg + o);
        }
        cpa16(sb + OFF_BN2 + (uint32_t)tid * 16,
              (const unsigned char*)(g_bn2 + bh * 1024) + tid * 16);
    }
    CPA_COMMIT();
    cpa_tile(sb + OFF_BUF + 0u,     khi_g, tid);
    cpa_tile(sb + OFF_BUF + 16384u, klo_g, tid);
    cpa_tile(sb + OFF_BUF + 32768u, v_g,   tid);
    CPA_COMMIT();
    {
        float* tvs = (float*)(smc + OFF_TOKV);
        for (int x = tid; x < 576; x += 256)
            tvs[(x >> 6) * 68 + (x & 63)] = g_tok[(x >> 6) * 192 + 128 + (x & 63)];
        if (tid < 128) ((int*)(smc + OFF_SEGQ))[tid] = mask[b * 1024 + t0 + tid];
    }
    asm volatile("cp.async.wait_group 1;" ::: "memory");   // Q/R/bn2 ready
    __syncthreads();

    const int m0w = w * 16;
    const int ci_lo = ((const int*)(smc + OFF_SEGQ))[m0w + g];
    const int ci_hi = ((const int*)(smc + OFF_SEGQ))[m0w + g + 8];
    const float* Rsm = (const float*)(smc + OFF_R);
    const float* bn2sm = (const float*)(smc + OFF_BN2);

    // ---- persistent Q A-fragments (hi & lo), 4 k-steps ----
    uint32_t qh[4][4], ql[4][4];
    {
        int kkA = (lane & 7) + ((lane >> 4) << 3);
        int mmA = m0w + ((lane >> 3) & 1) * 8;
#pragma unroll
        for (int k = 0; k < 4; k++) {
            uint32_t sw = SW((uint32_t)(16 * k + kkA) * 256 + mmA * 2);
            ldsm4t(qh[k], sb + OFF_QHI + sw);
            ldsm4t(ql[k], sb + OFF_QLO + sw);
        }
    }

    float accN[32], accC[32];
#pragma unroll
    for (int i = 0; i < 32; i++) { accN[i] = 0.f; accC[i] = 0.f; }
    float sNlo = 0.f, sNhi = 0.f, sClo = 0.f, sChi = 0.f;

    const int kkB = lane & 15, nnB8 = (lane >> 4) * 8;
    const int nnV = (lane >> 4) * 8 + (lane & 7), kkV8 = ((lane >> 3) & 1) * 8;

    for (int chk = 0; chk < 8; chk++) {
        const uint32_t bufb = OFF_BUF + (uint32_t)(chk & 1) * 49152u;
        __syncthreads();                       // everyone done with the other buffer
        if (chk + 1 < 8) {
            const uint32_t nb = OFF_BUF + (uint32_t)((chk + 1) & 1) * 49152u;
            cpa_tile(sb + nb + 0u,     khi_g + (chk + 1) * 16384, tid);
            cpa_tile(sb + nb + 16384u, klo_g + (chk + 1) * 16384, tid);
            cpa_tile(sb + nb + 32768u, v_g   + (chk + 1) * 16384, tid);
            CPA_COMMIT();
            asm volatile("cp.async.wait_group 1;" ::: "memory");
        } else {
            asm volatile("cp.async.wait_group 0;" ::: "memory");
        }
        __syncthreads();                       // current buffer visible to all

        const uint32_t bKHI = sb + bufb, bKLO = sb + bufb + 16384u, bV = sb + bufb + 32768u;
        const int s0 = chk * 128;

#pragma unroll
        for (int half = 0; half < 2; half++) {
            const int hb = half * 64;
            uint32_t WN0[8], WN1[8], WC0[8], WC1[8];
#pragma unroll
            for (int ntp = 0; ntp < 4; ntp++) {
                float S[8];
#pragma unroll
                for (int i = 0; i < 8; i++) S[i] = 0.f;
#pragma unroll
                for (int k = 0; k < 4; k++) {
                    uint32_t bh4[4], bl4[4];
                    uint32_t offK = SW((uint32_t)(16 * k + kkB) * 256 + (hb + ntp * 16 + nnB8) * 2);
                    ldsm4t(bh4, bKHI + offK);
                    ldsm4t(bl4, bKLO + offK);
                    hmma(S, qh[k], bh4[0], bh4[1]);
                    hmma(S, qh[k], bl4[0], bl4[1]);
                    hmma(S, ql[k], bh4[0], bh4[1]);
                    hmma(S + 4, qh[k], bh4[2], bh4[3]);
                    hmma(S + 4, qh[k], bl4[2], bl4[3]);
                    hmma(S + 4, ql[k], bh4[2], bh4[3]);
                }
#pragma unroll
                for (int t = 0; t < 2; t++) {
                    const int nt = 2 * ntp + t;
                    const int sA = s0 + hb + nt * 8 + 2 * tg;
                    float b2A = bn2sm[sA], b2B = bn2sm[sA + 1];
                    float e0 = ex2f(fmaf(S[4 * t + 0], SCL, b2A));
                    float e1 = ex2f(fmaf(S[4 * t + 1], SCL, b2B));
                    float e2 = ex2f(fmaf(S[4 * t + 2], SCL, b2A));
                    float e3 = ex2f(fmaf(S[4 * t + 3], SCL, b2B));
                    sNlo += e0 + e1; sNhi += e2 + e3;
                    WN0[nt] = packh2(e0, e1);
                    WN1[nt] = packh2(e2, e3);
                    float c0 = e0 * Rsm[sA * 8 + ci_lo];
                    float c1 = e1 * Rsm[(sA + 1) * 8 + ci_lo];
                    float c2 = e2 * Rsm[sA * 8 + ci_hi];
                    float c3 = e3 * Rsm[(sA + 1) * 8 + ci_hi];
                    sClo += c0 + c1; sChi += c2 + c3;
                    WC0[nt] = packh2(c0, c1);
                    WC1[nt] = packh2(c2, c3);
                }
            }
#pragma unroll
            for (int j = 0; j < 4; j++) {
                uint32_t aN[4] = { WN0[2 * j], WN1[2 * j], WN0[2 * j + 1], WN1[2 * j + 1] };
                uint32_t aC[4] = { WC0[2 * j], WC1[2 * j], WC0[2 * j + 1], WC1[2 * j + 1] };
                const int k0v = hb + j * 16;
#pragma unroll
                for (int np = 0; np < 4; np++) {
                    uint32_t bv[4];
                    ldsm4(bv, bV + SW((uint32_t)(np * 16 + nnV) * 256 + (k0v + kkV8) * 2));
                    hmma(accN + (2 * np) * 4, aN, bv[0], bv[1]);
                    hmma(accC + (2 * np) * 4, aC, bv[0], bv[1]);
                    hmma(accN + (2 * np + 1) * 4, aN, bv[2], bv[3]);
                    hmma(accC + (2 * np + 1) * 4, aC, bv[2], bv[3]);
                }
            }
        }
    }

    // ---- row-sum reduce across the 4 lanes sharing a row ----
#pragma unroll
    for (int o = 1; o < 4; o <<= 1) {
        sNlo += __shfl_xor_sync(0xffffffffu, sNlo, o);
        sNhi += __shfl_xor_sync(0xffffffffu, sNhi, o);
        sClo += __shfl_xor_sync(0xffffffffu, sClo, o);
        sChi += __shfl_xor_sync(0xffffffffu, sChi, o);
    }
    const float rsNlo = 0.5f / sNlo, rsNhi = 0.5f / sNhi;
    const float rsClo = 0.5f / sClo, rsChi = 0.5f / sChi;

    __syncthreads();   // all warps done reading buffers before OUT overlay

    // ---- stage normalized output to smem [64c][q] pitch 132 f32 ----
    {
        float* so = (float*)(smc + OFF_OUT);
        const float* tv8 = (const float*)(smc + OFF_TOKV) + 8 * 68;
        const float* tvl = (const float*)(smc + OFF_TOKV) + ci_lo * 68;
        const float* tvh = (const float*)(smc + OFF_TOKV) + ci_hi * 68;
#pragma unroll
        for (int nt = 0; nt < 8; nt++) {
            int c0 = nt * 8 + 2 * tg;
            so[c0 * 132 + m0w + g] =
                accN[nt * 4 + 0] * rsNlo + accC[nt * 4 + 0] * rsClo + 0.5f * (tv8[c0] + tvl[c0]);
            so[(c0 + 1) * 132 + m0w + g] =
                accN[nt * 4 + 1] * rsNlo + accC[nt * 4 + 1] * rsClo + 0.5f * (tv8[c0 + 1] + tvl[c0 + 1]);
            so[c0 * 132 + m0w + g + 8] =
                accN[nt * 4 + 2] * rsNhi + accC[nt * 4 + 2] * rsChi + 0.5f * (tv8[c0] + tvh[c0]);
            so[(c0 + 1) * 132 + m0w + g + 8] =
                accN[nt * 4 + 3] * rsNhi + accC[nt * 4 + 3] * rsChi + 0.5f * (tv8[c0 + 1] + tvh[c0 + 1]);
        }
    }
    __syncthreads();

    // ---- coalesced copy-out: out[c*65536 + bh*1024 + t] ----
    {
        const float* so = (const float*)(smc + OFF_OUT);
#pragma unroll
        for (int rep = 0; rep < 8; rep++) {
            int idx = rep * 256 + tid;
            int c = idx >> 5, q4 = (idx & 31) * 4;
            float4 v = *(const float4*)(so + c * 132 + q4);
            *(float4*)(out + c * 65536 + bh * 1024 + t0 + q4) = v;
        }
    }
}

// ---------------------------------------------------------------------------
extern "C" void kernel_launch(void* const* d_in, const int* in_sizes, int n_in,
                              void* d_out, int out_size)
{
    const float* qkv  = (const float*)d_in[0];
    const int*   mask = (const int*)  d_in[1];
    const float* emb  = (const float*)d_in[2];
    const float* Wc   = (const float*)d_in[3];
    float* out = (float*)d_out;

    preconv_kernel<<<12288, 256>>>(qkv);
    tok_kernel<<<dim3(9, 6), 256>>>(emb, Wc);
    bmat_kernel<<<dim3(64, 4), 256>>>(qkv, mask);
    cudaFuncSetAttribute(attn_kernel, cudaFuncAttributeMaxDynamicSharedMemorySize, SMEM_DYN);
    attn_kernel<<<dim3(8, 64), 256, SMEM_DYN>>>(qkv, mask, out);
}

// round 7
// speedup vs baseline: 11.5559x; 1.3380x over previous
#include <cuda_runtime.h>
#include <cuda_fp16.h>
#include <cstdint>

// ============================================================================
// out[t] = 0.5*( softmaxN(G+Bn)V + vn + softmaxC(G+Bc; seg==c_t)V + vc )
// G = Q.K^T via mma.sync HMMA, single fp16 pass (logit err ~2.5e-5, dominated
// by fp16 W rounding). Unnormalized exp2 weights repacked in-register as PV
// A-fragments; two fp32 accumulators; counter==2.
// R7: no hi/lo split (tensor work x0.67, ldmatrix /2), ring-3 cp.async,
// one barrier per chunk; preconverted working set fits in L2.
// ============================================================================

#define SCL 0.18033688011112042f   // 0.125 * log2(e)

__device__ float g_tok[9 * 192];
__device__ float g_R[64 * 1024 * 8];   // [bh][s][c] masked exp2(SCL*(Bc-Bn))
__device__ float g_bn2[64 * 1024];     // [bh][s] = SCL*Bn
// preconverted fp16 tiles: 16KB per tile, byte-image of the smem tile (swizzled)
__device__ __align__(16) unsigned char g_h16[64 * 2 * 8 * 16384];  // [bh][q/k][tile]
__device__ __align__(16) unsigned char g_vh[64 * 8 * 16384];       // [bh][tile]

__device__ __forceinline__ uint32_t smem_u32(const void* p) {
    uint32_t a;
    asm("{ .reg .u64 t; cvta.to.shared.u64 t, %1; cvt.u32.u64 %0, t; }" : "=r"(a) : "l"(p));
    return a;
}
__device__ __forceinline__ float ex2f(float x) {
    float y; asm("ex2.approx.f32 %0, %1;" : "=f"(y) : "f"(x)); return y;
}
__device__ __forceinline__ uint32_t packh2(float lo, float hi) {
    uint32_t r; asm("cvt.rn.f16x2.f32 %0, %1, %2;" : "=r"(r) : "f"(hi), "f"(lo)); return r;
}
__device__ __forceinline__ uint32_t SW(uint32_t off) {      // 256B-pitch swizzle
    return off ^ ((off >> 4) & 0x70);
}
__device__ __forceinline__ void ldsm4t(uint32_t* r, uint32_t addr) {
    asm volatile("ldmatrix.sync.aligned.m8n8.x4.trans.shared.b16 {%0,%1,%2,%3}, [%4];"
        : "=r"(r[0]), "=r"(r[1]), "=r"(r[2]), "=r"(r[3]) : "r"(addr));
}
__device__ __forceinline__ void ldsm4(uint32_t* r, uint32_t addr) {
    asm volatile("ldmatrix.sync.aligned.m8n8.x4.shared.b16 {%0,%1,%2,%3}, [%4];"
        : "=r"(r[0]), "=r"(r[1]), "=r"(r[2]), "=r"(r[3]) : "r"(addr));
}
__device__ __forceinline__ void hmma(float* c, const uint32_t* a, uint32_t b0, uint32_t b1) {
    asm volatile("mma.sync.aligned.m16n8k16.row.col.f32.f16.f16.f32 "
        "{%0,%1,%2,%3},{%4,%5,%6,%7},{%8,%9},{%0,%1,%2,%3};"
        : "+f"(c[0]), "+f"(c[1]), "+f"(c[2]), "+f"(c[3])
        : "r"(a[0]), "r"(a[1]), "r"(a[2]), "r"(a[3]), "r"(b0), "r"(b1));
}
#define CPA_COMMIT() asm volatile("cp.async.commit_group;" ::: "memory")
__device__ __forceinline__ void cpa16(uint32_t dst, const void* src) {
    asm volatile("cp.async.cg.shared.global [%0], [%1], 16;" :: "r"(dst), "l"(src) : "memory");
}
__device__ __forceinline__ void cpa_tile(uint32_t dst, const unsigned char* src, int tid) {
#pragma unroll
    for (int rep = 0; rep < 4; rep++) {
        uint32_t o = (uint32_t)(rep * 256 + tid) * 16;
        cpa16(dst + o, src + o);
    }
}

// ---------------- preconvert: qkv f32 -> swizzled fp16 tile images ----------------
__global__ void preconv_kernel(const float* __restrict__ qkv)
{
    int idx = blockIdx.x * 256 + threadIdx.x;          // 64*192*256 total
    int t4 = (idx & 255) * 4;
    int ch = (idx >> 8) % 192;
    int bh = idx / (256 * 192);
    float4 v = *(const float4*)(qkv + (size_t)bh * 196608 + ch * 1024 + t4);
    uint32_t h0 = packh2(v.x, v.y), h1 = packh2(v.z, v.w);
    int tile = t4 >> 7, s = t4 & 127;
    if (ch < 128) {
        int p = ch >> 6, c = ch & 63;
        uint32_t off = SW((uint32_t)c * 256 + s * 2);
        size_t base = ((size_t)(bh * 2 + p) * 8 + tile) * 16384;
        *(uint2*)(g_h16 + base + off) = make_uint2(h0, h1);
    } else {
        int c = ch - 128;
        uint32_t off = SW((uint32_t)c * 256 + s * 2);
        size_t base = ((size_t)bh * 8 + tile) * 16384;
        *(uint2*)(g_vh + base + off) = make_uint2(h0, h1);
    }
}

// ---------------- aux A: class tokens (grid 9 x 6, 4 rows/warp) ----------------
__global__ void tok_kernel(const float* __restrict__ emb, const float* __restrict__ Wc)
{
    __shared__ float e[512];
    int c9 = blockIdx.x;
    for (int k = threadIdx.x; k < 512; k += 256) e[k] = emb[c9 * 512 + k];
    __syncthreads();
    int w = threadIdx.x >> 5, l = threadIdx.x & 31;
#pragma unroll
    for (int rr = 0; rr < 4; rr++) {
        int r = blockIdx.y * 32 + w * 4 + rr;
        const float* wr = Wc + r * 512;
        float acc = 0.f;
#pragma unroll
        for (int k = 0; k < 16; k++) acc = fmaf(wr[l + 32 * k], e[l + 32 * k], acc);
#pragma unroll
        for (int o = 16; o > 0; o >>= 1) acc += __shfl_xor_sync(0xffffffffu, acc, o);
        if (l == 0) g_tok[c9 * 192 + r] = acc;
    }
}

// ---------------- aux B: bn2 + masked exp2 ratio table (grid 64 x 4) ----------------
__global__ void bmat_kernel(const float* __restrict__ qkv, const int* __restrict__ mask)
{
    __shared__ float tq[9 * 64];
    int bh = blockIdx.x, b = bh >> 3;
    for (int x = threadIdx.x; x < 576; x += 256) tq[x] = g_tok[(x >> 6) * 192 + (x & 63)];
    __syncthreads();
    const float* kb = qkv + bh * 196608 + 65536;
    int s = blockIdx.y * 256 + threadIdx.x;
    float acc[9];
#pragma unroll
    for (int c = 0; c < 9; c++) acc[c] = 0.f;
#pragma unroll 4
    for (int c = 0; c < 64; c++) {
        float kv = kb[c * 1024 + s];
#pragma unroll
        for (int c9 = 0; c9 < 9; c9++) acc[c9] = fmaf(tq[c9 * 64 + c], kv, acc[c9]);
    }
    float bn = acc[8];
    g_bn2[bh * 1024 + s] = SCL * bn;
    int sg = mask[b * 1024 + s];
    float r[8];
#pragma unroll
    for (int c = 0; c < 8; c++) r[c] = (sg == c) ? ex2f(SCL * (acc[c] - bn)) : 0.f;
    float4* dst = (float4*)(g_R + bh * 8192 + s * 8);
    dst[0] = make_float4(r[0], r[1], r[2], r[3]);
    dst[1] = make_float4(r[4], r[5], r[6], r[7]);
}

// ---------------- main kernel ----------------
#define OFF_QH    0u
#define OFF_BUF   16384u          /* ring-3: (K 16K + V 16K) x3 = 96KB */
#define OFF_R     114688u
#define OFF_BN2   147456u
#define OFF_TOKV  151552u         /* [9][68] f32 */
#define OFF_SEGQ  154000u
#define OFF_OUT   16384u          /* overlay on buffers after mainloop */
#define SMEM_DYN  154624

__global__ void __launch_bounds__(256, 1)
attn_kernel(const float* __restrict__ qkv, const int* __restrict__ mask,
            float* __restrict__ out)
{
    extern __shared__ __align__(16) char smc[];
    const uint32_t sb = smem_u32(smc);

    const int tid = threadIdx.x;
    const int w = tid >> 5, lane = tid & 31;
    const int g = lane >> 2, tg = lane & 3;
    const int bh = blockIdx.y;
    const int qt = blockIdx.x;
    const int t0 = qt * 128;
    const int b = bh >> 3;

    const unsigned char* q_g = g_h16 + ((size_t)(bh * 2) * 8 + qt) * 16384;
    const unsigned char* k_g = g_h16 + ((size_t)(bh * 2 + 1) * 8) * 16384;
    const unsigned char* v_g = g_vh + ((size_t)bh * 8) * 16384;

    // ---- prologue: G0 = Q + R + bn2 ; G1 = chunk0 ; G2 = chunk1 ----
    cpa_tile(sb + OFF_QH, q_g, tid);
    {
        const unsigned char* Rg = (const unsigned char*)(g_R + bh * 8192);
#pragma unroll
        for (int rep = 0; rep < 8; rep++) {
            uint32_t o = (uint32_t)(rep * 256 + tid) * 16;
            cpa16(sb + OFF_R + o, Rg + o);
        }
        cpa16(sb + OFF_BN2 + (uint32_t)tid * 16,
              (const unsigned char*)(g_bn2 + bh * 1024) + tid * 16);
    }
    CPA_COMMIT();
    cpa_tile(sb + OFF_BUF + 0u,     k_g, tid);
    cpa_tile(sb + OFF_BUF + 16384u, v_g, tid);
    CPA_COMMIT();
    cpa_tile(sb + OFF_BUF + 32768u, k_g + 16384, tid);
    cpa_tile(sb + OFF_BUF + 49152u, v_g + 16384, tid);
    CPA_COMMIT();
    {
        float* tvs = (float*)(smc + OFF_TOKV);
        for (int x = tid; x < 576; x += 256)
            tvs[(x >> 6) * 68 + (x & 63)] = g_tok[(x >> 6) * 192 + 128 + (x & 63)];
        if (tid < 128) ((int*)(smc + OFF_SEGQ))[tid] = mask[b * 1024 + t0 + tid];
    }
    asm volatile("cp.async.wait_group 2;" ::: "memory");   // Q/R/bn2 ready
    __syncthreads();

    const int m0w = w * 16;
    const int ci_lo = ((const int*)(smc + OFF_SEGQ))[m0w + g];
    const int ci_hi = ((const int*)(smc + OFF_SEGQ))[m0w + g + 8];
    const float* Rsm = (const float*)(smc + OFF_R);
    const float* bn2sm = (const float*)(smc + OFF_BN2);

    // ---- persistent Q A-fragments, 4 k-steps ----
    uint32_t qh[4][4];
    {
        int kkA = (lane & 7) + ((lane >> 4) << 3);
        int mmA = m0w + ((lane >> 3) & 1) * 8;
#pragma unroll
        for (int k = 0; k < 4; k++)
            ldsm4t(qh[k], sb + OFF_QH + SW((uint32_t)(16 * k + kkA) * 256 + mmA * 2));
    }

    float accN[32], accC[32];
#pragma unroll
    for (int i = 0; i < 32; i++) { accN[i] = 0.f; accC[i] = 0.f; }
    float sNlo = 0.f, sNhi = 0.f, sClo = 0.f, sChi = 0.f;

    const int kkB = lane & 15, nnB8 = (lane >> 4) * 8;
    const int nnV = (lane >> 4) * 8 + (lane & 7), kkV8 = ((lane >> 3) & 1) * 8;

    for (int chk = 0; chk < 8; chk++) {
        if (chk < 7) { asm volatile("cp.async.wait_group 1;" ::: "memory"); }
        else         { asm volatile("cp.async.wait_group 0;" ::: "memory"); }
        __syncthreads();          // chunk chk visible to all; ring slot (chk+2)%3 free
        if (chk + 2 < 8) {
            const uint32_t nb = OFF_BUF + (uint32_t)((chk + 2) % 3) * 32768u;
            cpa_tile(sb + nb + 0u,     k_g + (chk + 2) * 16384, tid);
            cpa_tile(sb + nb + 16384u, v_g + (chk + 2) * 16384, tid);
            CPA_COMMIT();
        }

        const uint32_t bufb = OFF_BUF + (uint32_t)(chk % 3) * 32768u;
        const uint32_t bKH = sb + bufb, bV = sb + bufb + 16384u;
        const int s0 = chk * 128;

#pragma unroll
        for (int half = 0; half < 2; half++) {
            const int hb = half * 64;
            uint32_t WN0[8], WN1[8], WC0[8], WC1[8];
#pragma unroll
            for (int ntp = 0; ntp < 4; ntp++) {
                float S[8];
#pragma unroll
                for (int i = 0; i < 8; i++) S[i] = 0.f;
#pragma unroll
                for (int k = 0; k < 4; k++) {
                    uint32_t bh4[4];
                    ldsm4t(bh4, bKH + SW((uint32_t)(16 * k + kkB) * 256 + (hb + ntp * 16 + nnB8) * 2));
                    hmma(S, qh[k], bh4[0], bh4[1]);
                    hmma(S + 4, qh[k], bh4[2], bh4[3]);
                }
#pragma unroll
                for (int t = 0; t < 2; t++) {
                    const int nt = 2 * ntp + t;
                    const int sA = s0 + hb + nt * 8 + 2 * tg;
                    float b2A = bn2sm[sA], b2B = bn2sm[sA + 1];
                    float e0 = ex2f(fmaf(S[4 * t + 0], SCL, b2A));
                    float e1 = ex2f(fmaf(S[4 * t + 1], SCL, b2B));
                    float e2 = ex2f(fmaf(S[4 * t + 2], SCL, b2A));
                    float e3 = ex2f(fmaf(S[4 * t + 3], SCL, b2B));
                    sNlo += e0 + e1; sNhi += e2 + e3;
                    WN0[nt] = packh2(e0, e1);
                    WN1[nt] = packh2(e2, e3);
                    float c0 = e0 * Rsm[sA * 8 + ci_lo];
                    float c1 = e1 * Rsm[(sA + 1) * 8 + ci_lo];
                    float c2 = e2 * Rsm[sA * 8 + ci_hi];
                    float c3 = e3 * Rsm[(sA + 1) * 8 + ci_hi];
                    sClo += c0 + c1; sChi += c2 + c3;
                    WC0[nt] = packh2(c0, c1);
                    WC1[nt] = packh2(c2, c3);
                }
            }
#pragma unroll
            for (int j = 0; j < 4; j++) {
                uint32_t aN[4] = { WN0[2 * j], WN1[2 * j], WN0[2 * j + 1], WN1[2 * j + 1] };
                uint32_t aC[4] = { WC0[2 * j], WC1[2 * j], WC0[2 * j + 1], WC1[2 * j + 1] };
                const int k0v = hb + j * 16;
#pragma unroll
                for (int np = 0; np < 4; np++) {
                    uint32_t bv[4];
                    ldsm4(bv, bV + SW((uint32_t)(np * 16 + nnV) * 256 + (k0v + kkV8) * 2));
                    hmma(accN + (2 * np) * 4, aN, bv[0], bv[1]);
                    hmma(accC + (2 * np) * 4, aC, bv[0], bv[1]);
                    hmma(accN + (2 * np + 1) * 4, aN, bv[2], bv[3]);
                    hmma(accC + (2 * np + 1) * 4, aC, bv[2], bv[3]);
                }
            }
        }
    }

    // ---- row-sum reduce across the 4 lanes sharing a row ----
#pragma unroll
    for (int o = 1; o < 4; o <<= 1) {
        sNlo += __shfl_xor_sync(0xffffffffu, sNlo, o);
        sNhi += __shfl_xor_sync(0xffffffffu, sNhi, o);
        sClo += __shfl_xor_sync(0xffffffffu, sClo, o);
        sChi += __shfl_xor_sync(0xffffffffu, sChi, o);
    }
    const float rsNlo = 0.5f / sNlo, rsNhi = 0.5f / sNhi;
    const float rsClo = 0.5f / sClo, rsChi = 0.5f / sChi;

    __syncthreads();   // all warps done reading buffers before OUT overlay

    // ---- stage normalized output to smem [64c][q] pitch 132 f32 ----
    {
        float* so = (float*)(smc + OFF_OUT);
        const float* tv8 = (const float*)(smc + OFF_TOKV) + 8 * 68;
        const float* tvl = (const float*)(smc + OFF_TOKV) + ci_lo * 68;
        const float* tvh = (const float*)(smc + OFF_TOKV) + ci_hi * 68;
#pragma unroll
        for (int nt = 0; nt < 8; nt++) {
            int c0 = nt * 8 + 2 * tg;
            so[c0 * 132 + m0w + g] =
                accN[nt * 4 + 0] * rsNlo + accC[nt * 4 + 0] * rsClo + 0.5f * (tv8[c0] + tvl[c0]);
            so[(c0 + 1) * 132 + m0w + g] =
                accN[nt * 4 + 1] * rsNlo + accC[nt * 4 + 1] * rsClo + 0.5f * (tv8[c0 + 1] + tvl[c0 + 1]);
            so[c0 * 132 + m0w + g + 8] =
                accN[nt * 4 + 2] * rsNhi + accC[nt * 4 + 2] * rsChi + 0.5f * (tv8[c0] + tvh[c0]);
            so[(c0 + 1) * 132 + m0w + g + 8] =
                accN[nt * 4 + 3] * rsNhi + accC[nt * 4 + 3] * rsChi + 0.5f * (tv8[c0 + 1] + tvh[c0 + 1]);
        }
    }
    __syncthreads();

    // ---- coalesced copy-out: out[c*65536 + bh*1024 + t] ----
    {
        const float* so = (const float*)(smc + OFF_OUT);
#pragma unroll
        for (int rep = 0; rep < 8; rep++) {
            int idx = rep * 256 + tid;
            int c = idx >> 5, q4 = (idx & 31) * 4;
            float4 v = *(const float4*)(so + c * 132 + q4);
            *(float4*)(out + c * 65536 + bh * 1024 + t0 + q4) = v;
        }
    }
}

// ---------------------------------------------------------------------------
extern "C" void kernel_launch(void* const* d_in, const int* in_sizes, int n_in,
                              void* d_out, int out_size)
{
    const float* qkv  = (const float*)d_in[0];
    const int*   mask = (const int*)  d_in[1];
    const float* emb  = (const float*)d_in[2];
    const float* Wc   = (const float*)d_in[3];
    float* out = (float*)d_out;

    preconv_kernel<<<12288, 256>>>(qkv);
    tok_kernel<<<dim3(9, 6), 256>>>(emb, Wc);
    bmat_kernel<<<dim3(64, 4), 256>>>(qkv, mask);
    cudaFuncSetAttribute(attn_kernel, cudaFuncAttributeMaxDynamicSharedMemorySize, SMEM_DYN);
    attn_kernel<<<dim3(8, 64), 256, SMEM_DYN>>>(qkv, mask, out);
}

// round 8
// speedup vs baseline: 11.7333x; 1.0153x over previous
#include <cuda_runtime.h>
#include <cuda_fp16.h>
#include <cstdint>

// ============================================================================
// out[t] = 0.5*( softmaxN(G+Bn)V + vn + softmaxC(G+Bc; seg==c_t)V + vc )
// G = Q.K^T via mma.sync HMMA fp16. Unnormalized exp2 weights repacked
// in-register as PV A-fragments; two fp32 accumulators; counter==2.
// R8: 128-thread CTAs / 64-q tiles, 2 CTAs/SM (RF-exact), fused QK->exp->PV
// per ntp (no W staging arrays), transposed ratio table (float2 LDS).
// ============================================================================

#define SCL 0.18033688011112042f   // 0.125 * log2(e)

__device__ float g_tok[9 * 192];
__device__ float g_Rt[64 * 8 * 1024];  // [bh][c][s] masked exp2(SCL*(Bc-Bn))
__device__ float g_bn2[64 * 1024];     // [bh][s] = SCL*Bn
// preconverted fp16 tile images (swizzled smem byte-images)
__device__ __align__(16) unsigned char g_q16[64 * 16 * 8192];   // [bh][qtile 64t]
__device__ __align__(16) unsigned char g_k16[64 * 8 * 16384];   // [bh][ktile 128s]
__device__ __align__(16) unsigned char g_vh [64 * 8 * 16384];   // [bh][vtile 128s]

__device__ __forceinline__ uint32_t smem_u32(const void* p) {
    uint32_t a;
    asm("{ .reg .u64 t; cvta.to.shared.u64 t, %1; cvt.u32.u64 %0, t; }" : "=r"(a) : "l"(p));
    return a;
}
__device__ __forceinline__ float ex2f(float x) {
    float y; asm("ex2.approx.f32 %0, %1;" : "=f"(y) : "f"(x)); return y;
}
__device__ __forceinline__ uint32_t packh2(float lo, float hi) {
    uint32_t r; asm("cvt.rn.f16x2.f32 %0, %1, %2;" : "=r"(r) : "f"(hi), "f"(lo)); return r;
}
__device__ __forceinline__ uint32_t SW(uint32_t off) {      // 256B-pitch swizzle
    return off ^ ((off >> 4) & 0x70);
}
__device__ __forceinline__ void ldsm4t(uint32_t* r, uint32_t addr) {
    asm volatile("ldmatrix.sync.aligned.m8n8.x4.trans.shared.b16 {%0,%1,%2,%3}, [%4];"
        : "=r"(r[0]), "=r"(r[1]), "=r"(r[2]), "=r"(r[3]) : "r"(addr));
}
__device__ __forceinline__ void ldsm4(uint32_t* r, uint32_t addr) {
    asm volatile("ldmatrix.sync.aligned.m8n8.x4.shared.b16 {%0,%1,%2,%3}, [%4];"
        : "=r"(r[0]), "=r"(r[1]), "=r"(r[2]), "=r"(r[3]) : "r"(addr));
}
__device__ __forceinline__ void hmma(float* c, const uint32_t* a, uint32_t b0, uint32_t b1) {
    asm volatile("mma.sync.aligned.m16n8k16.row.col.f32.f16.f16.f32 "
        "{%0,%1,%2,%3},{%4,%5,%6,%7},{%8,%9},{%0,%1,%2,%3};"
        : "+f"(c[0]), "+f"(c[1]), "+f"(c[2]), "+f"(c[3])
        : "r"(a[0]), "r"(a[1]), "r"(a[2]), "r"(a[3]), "r"(b0), "r"(b1));
}
#define CPA_COMMIT() asm volatile("cp.async.commit_group;" ::: "memory")
__device__ __forceinline__ void cpa16(uint32_t dst, const void* src) {
    asm volatile("cp.async.cg.shared.global [%0], [%1], 16;" :: "r"(dst), "l"(src) : "memory");
}
__device__ __forceinline__ void cpa_tile16k(uint32_t dst, const unsigned char* src, int tid) {
#pragma unroll
    for (int rep = 0; rep < 8; rep++) {
        uint32_t o = (uint32_t)(rep * 128 + tid) * 16;
        cpa16(dst + o, src + o);
    }
}

// ---------------- preconvert: qkv f32 -> swizzled fp16 tile images ----------------
__global__ void preconv_kernel(const float* __restrict__ qkv)
{
    int idx = blockIdx.x * 256 + threadIdx.x;          // 64*192*256 total
    int t4 = (idx & 255) * 4;
    int ch = (idx >> 8) % 192;
    int bh = idx / (256 * 192);
    float4 v = *(const float4*)(qkv + (size_t)bh * 196608 + ch * 1024 + t4);
    uint32_t h0 = packh2(v.x, v.y), h1 = packh2(v.z, v.w);
    if (ch < 64) {                    // Q: 8KB tiles of 64 t
        int tile = t4 >> 6, s = t4 & 63;
        uint32_t off = (uint32_t)ch * 128 + ((uint32_t)(s * 2) ^ (((uint32_t)ch & 7) << 4));
        size_t base = ((size_t)bh * 16 + tile) * 8192;
        *(uint2*)(g_q16 + base + off) = make_uint2(h0, h1);
    } else if (ch < 128) {            // K: 16KB tiles of 128 s
        int c = ch - 64;
        int tile = t4 >> 7, s = t4 & 127;
        uint32_t off = SW((uint32_t)c * 256 + s * 2);
        size_t base = ((size_t)bh * 8 + tile) * 16384;
        *(uint2*)(g_k16 + base + off) = make_uint2(h0, h1);
    } else {                          // V
        int c = ch - 128;
        int tile = t4 >> 7, s = t4 & 127;
        uint32_t off = SW((uint32_t)c * 256 + s * 2);
        size_t base = ((size_t)bh * 8 + tile) * 16384;
        *(uint2*)(g_vh + base + off) = make_uint2(h0, h1);
    }
}

// ---------------- aux A: class tokens (grid 9 x 6, 4 rows/warp) ----------------
__global__ void tok_kernel(const float* __restrict__ emb, const float* __restrict__ Wc)
{
    __shared__ float e[512];
    int c9 = blockIdx.x;
    for (int k = threadIdx.x; k < 512; k += 256) e[k] = emb[c9 * 512 + k];
    __syncthreads();
    int w = threadIdx.x >> 5, l = threadIdx.x & 31;
#pragma unroll
    for (int rr = 0; rr < 4; rr++) {
        int r = blockIdx.y * 32 + w * 4 + rr;
        const float* wr = Wc + r * 512;
        float acc = 0.f;
#pragma unroll
        for (int k = 0; k < 16; k++) acc = fmaf(wr[l + 32 * k], e[l + 32 * k], acc);
#pragma unroll
        for (int o = 16; o > 0; o >>= 1) acc += __shfl_xor_sync(0xffffffffu, acc, o);
        if (l == 0) g_tok[c9 * 192 + r] = acc;
    }
}

// ---------------- aux B: bn2 + transposed masked exp2 ratio table ----------------
__global__ void bmat_kernel(const float* __restrict__ qkv, const int* __restrict__ mask)
{
    __shared__ float tq[9 * 64];
    int bh = blockIdx.x, b = bh >> 3;
    for (int x = threadIdx.x; x < 576; x += 256) tq[x] = g_tok[(x >> 6) * 192 + (x & 63)];
    __syncthreads();
    const float* kb = qkv + bh * 196608 + 65536;
    int s = blockIdx.y * 256 + threadIdx.x;
    float acc[9];
#pragma unroll
    for (int c = 0; c < 9; c++) acc[c] = 0.f;
#pragma unroll 4
    for (int c = 0; c < 64; c++) {
        float kv = kb[c * 1024 + s];
#pragma unroll
        for (int c9 = 0; c9 < 9; c9++) acc[c9] = fmaf(tq[c9 * 64 + c], kv, acc[c9]);
    }
    float bn = acc[8];
    g_bn2[bh * 1024 + s] = SCL * bn;
    int sg = mask[b * 1024 + s];
#pragma unroll
    for (int c = 0; c < 8; c++)
        g_Rt[bh * 8192 + c * 1024 + s] = (sg == c) ? ex2f(SCL * (acc[c] - bn)) : 0.f;
}

// ---------------- main kernel ----------------
#define OFF_QH    0u
#define OFF_BUF   8192u           /* ring-2: (K 16K + V 16K) x2 = 64KB */
#define OFF_R     73728u          /* Rt [8][1032] f32 = 33024B */
#define OFF_BN2   106752u
#define OFF_TOKV  110848u         /* [9][68] f32 */
#define OFF_SEGQ  113296u
#define OFF_OUT   8192u           /* overlay on buffers after mainloop */
#define SMEM_DYN  113664

__global__ void __launch_bounds__(128, 2)
attn_kernel(const float* __restrict__ qkv, const int* __restrict__ mask,
            float* __restrict__ out)
{
    extern __shared__ __align__(16) char smc[];
    const uint32_t sb = smem_u32(smc);

    const int tid = threadIdx.x;
    const int w = tid >> 5, lane = tid & 31;
    const int g = lane >> 2, tg = lane & 3;
    const int bh = blockIdx.y;
    const int qt = blockIdx.x;                 // 0..15 (64-row tiles)
    const int t0 = qt * 64;
    const int b = bh >> 3;

    const unsigned char* q_g = g_q16 + ((size_t)bh * 16 + qt) * 8192;
    const unsigned char* k_g = g_k16 + ((size_t)bh * 8) * 16384;
    const unsigned char* v_g = g_vh + ((size_t)bh * 8) * 16384;

    // ---- prologue: G0 = Q + Rt + bn2 ; G1 = chunk0 ; G2 = chunk1 ----
#pragma unroll
    for (int rep = 0; rep < 4; rep++) {
        uint32_t o = (uint32_t)(rep * 128 + tid) * 16;
        cpa16(sb + OFF_QH + o, q_g + o);
    }
    {
        const unsigned char* Rg = (const unsigned char*)(g_Rt + bh * 8192);
#pragma unroll
        for (int rep = 0; rep < 16; rep++) {
            int idx = rep * 128 + tid;              // 0..2047
            int row = idx >> 8, o16 = idx & 255;
            cpa16(sb + OFF_R + (uint32_t)row * 4128u + (uint32_t)o16 * 16u,
                  Rg + row * 4096 + o16 * 16);
        }
#pragma unroll
        for (int rep = 0; rep < 2; rep++) {
            uint32_t o = (uint32_t)(rep * 128 + tid) * 16;
            cpa16(sb + OFF_BN2 + o, (const unsigned char*)(g_bn2 + bh * 1024) + o);
        }
    }
    CPA_COMMIT();
    cpa_tile16k(sb + OFF_BUF + 0u,     k_g, tid);
    cpa_tile16k(sb + OFF_BUF + 16384u, v_g, tid);
    CPA_COMMIT();
    cpa_tile16k(sb + OFF_BUF + 32768u, k_g + 16384, tid);
    cpa_tile16k(sb + OFF_BUF + 49152u, v_g + 16384, tid);
    CPA_COMMIT();
    {
        float* tvs = (float*)(smc + OFF_TOKV);
        for (int x = tid; x < 576; x += 128)
            tvs[(x >> 6) * 68 + (x & 63)] = g_tok[(x >> 6) * 192 + 128 + (x & 63)];
        if (tid < 64) ((int*)(smc + OFF_SEGQ))[tid] = mask[b * 1024 + t0 + tid];
    }
    asm volatile("cp.async.wait_group 2;" ::: "memory");   // Q/Rt/bn2 ready
    __syncthreads();

    const int m0w = w * 16;
    const int ci_lo = ((const int*)(smc + OFF_SEGQ))[m0w + g];
    const int ci_hi = ((const int*)(smc + OFF_SEGQ))[m0w + g + 8];
    const float* Rt = (const float*)(smc + OFF_R);
    const float* bn2sm = (const float*)(smc + OFF_BN2);

    // ---- persistent Q A-fragments (pitch-128 swizzle), 4 k-steps ----
    uint32_t qh[4][4];
    {
        int kkA = (lane & 7) + ((lane >> 4) << 3);
        int mmA = m0w + ((lane >> 3) & 1) * 8;
#pragma unroll
        for (int k = 0; k < 4; k++) {
            uint32_t c = (uint32_t)(16 * k + kkA);
            uint32_t a = c * 128 + (((uint32_t)mmA * 2) ^ ((c & 7) << 4));
            ldsm4t(qh[k], sb + OFF_QH + a);
        }
    }

    float accN[32], accC[32];
#pragma unroll
    for (int i = 0; i < 32; i++) { accN[i] = 0.f; accC[i] = 0.f; }
    float sNlo = 0.f, sNhi = 0.f, sClo = 0.f, sChi = 0.f;

    const int kkB = lane & 15, nnB8 = (lane >> 4) * 8;
    const int nnV = (lane >> 4) * 8 + (lane & 7), kkV8 = ((lane >> 3) & 1) * 8;

    for (int chk = 0; chk < 8; chk++) {
        if (chk < 7) { asm volatile("cp.async.wait_group 1;" ::: "memory"); }
        else         { asm volatile("cp.async.wait_group 0;" ::: "memory"); }
        __syncthreads();                       // chunk chk visible to all

        const uint32_t bufb = OFF_BUF + (uint32_t)(chk & 1) * 32768u;
        const uint32_t bKH = sb + bufb, bV = sb + bufb + 16384u;
        const int s0 = chk * 128;

#pragma unroll
        for (int half = 0; half < 2; half++) {
            const int hb = half * 64;
#pragma unroll
            for (int ntp = 0; ntp < 4; ntp++) {
                float S[8];
#pragma unroll
                for (int i = 0; i < 8; i++) S[i] = 0.f;
#pragma unroll
                for (int k = 0; k < 4; k++) {
                    uint32_t bh4[4];
                    ldsm4t(bh4, bKH + SW((uint32_t)(16 * k + kkB) * 256 + (hb + ntp * 16 + nnB8) * 2));
                    hmma(S, qh[k], bh4[0], bh4[1]);
                    hmma(S + 4, qh[k], bh4[2], bh4[3]);
                }
                uint32_t aN[4], aC[4];
#pragma unroll
                for (int t = 0; t < 2; t++) {
                    const int sA = s0 + hb + (2 * ntp + t) * 8 + 2 * tg;
                    float2 b2 = *(const float2*)(bn2sm + sA);
                    float e0 = ex2f(fmaf(S[4 * t + 0], SCL, b2.x));
                    float e1 = ex2f(fmaf(S[4 * t + 1], SCL, b2.y));
                    float e2 = ex2f(fmaf(S[4 * t + 2], SCL, b2.x));
                    float e3 = ex2f(fmaf(S[4 * t + 3], SCL, b2.y));
                    sNlo += e0 + e1; sNhi += e2 + e3;
                    aN[t] = packh2(e0, e1);
                    aN[t + 2] = packh2(e2, e3);
                    float2 rl = *(const float2*)(Rt + ci_lo * 1032 + sA);
                    float2 rh = *(const float2*)(Rt + ci_hi * 1032 + sA);
                    float c0 = e0 * rl.x, c1 = e1 * rl.y;
                    float c2 = e2 * rh.x, c3 = e3 * rh.y;
                    sClo += c0 + c1; sChi += c2 + c3;
                    aC[t] = packh2(c0, c1);
                    aC[t + 2] = packh2(c2, c3);
                }
                // swap to A-frag order {t0, hi0, t1, hi1}
                uint32_t tmp;
                tmp = aN[1]; aN[1] = aN[2]; aN[2] = tmp;
                tmp = aC[1]; aC[1] = aC[2]; aC[2] = tmp;
                // PV for this 16-s group
                const int k0v = hb + ntp * 16;
#pragma unroll
                for (int np = 0; np < 4; np++) {
                    uint32_t bv[4];
                    ldsm4(bv, bV + SW((uint32_t)(np * 16 + nnV) * 256 + (k0v + kkV8) * 2));
                    hmma(accN + (2 * np) * 4, aN, bv[0], bv[1]);
                    hmma(accC + (2 * np) * 4, aC, bv[0], bv[1]);
                    hmma(accN + (2 * np + 1) * 4, aN, bv[2], bv[3]);
                    hmma(accC + (2 * np + 1) * 4, aC, bv[2], bv[3]);
                }
            }
        }
        __syncthreads();                       // slot chk&1 fully consumed
        if (chk + 2 < 8) {
            const uint32_t nb = OFF_BUF + (uint32_t)(chk & 1) * 32768u;
            cpa_tile16k(sb + nb + 0u,     k_g + (chk + 2) * 16384, tid);
            cpa_tile16k(sb + nb + 16384u, v_g + (chk + 2) * 16384, tid);
            CPA_COMMIT();
        }
    }

    // ---- row-sum reduce across the 4 lanes sharing a row ----
#pragma unroll
    for (int o = 1; o < 4; o <<= 1) {
        sNlo += __shfl_xor_sync(0xffffffffu, sNlo, o);
        sNhi += __shfl_xor_sync(0xffffffffu, sNhi, o);
        sClo += __shfl_xor_sync(0xffffffffu, sClo, o);
        sChi += __shfl_xor_sync(0xffffffffu, sChi, o);
    }
    const float rsNlo = 0.5f / sNlo, rsNhi = 0.5f / sNhi;
    const float rsClo = 0.5f / sClo, rsChi = 0.5f / sChi;

    // ---- stage normalized output to smem [64c][64q] pitch 68 f32 ----
    {
        float* so = (float*)(smc + OFF_OUT);
        const float* tv8 = (const float*)(smc + OFF_TOKV) + 8 * 68;
        const float* tvl = (const float*)(smc + OFF_TOKV) + ci_lo * 68;
        const float* tvh = (const float*)(smc + OFF_TOKV) + ci_hi * 68;
#pragma unroll
        for (int nt = 0; nt < 8; nt++) {
            int c0 = nt * 8 + 2 * tg;
            so[c0 * 68 + m0w + g] =
                accN[nt * 4 + 0] * rsNlo + accC[nt * 4 + 0] * rsClo + 0.5f * (tv8[c0] + tvl[c0]);
            so[(c0 + 1) * 68 + m0w + g] =
                accN[nt * 4 + 1] * rsNlo + accC[nt * 4 + 1] * rsClo + 0.5f * (tv8[c0 + 1] + tvl[c0 + 1]);
            so[c0 * 68 + m0w + g + 8] =
                accN[nt * 4 + 2] * rsNhi + accC[nt * 4 + 2] * rsChi + 0.5f * (tv8[c0] + tvh[c0]);
            so[(c0 + 1) * 68 + m0w + g + 8] =
                accN[nt * 4 + 3] * rsNhi + accC[nt * 4 + 3] * rsChi + 0.5f * (tv8[c0 + 1] + tvh[c0 + 1]);
        }
    }
    __syncthreads();

    // ---- coalesced copy-out: out[c*65536 + bh*1024 + t0 + t] ----
    {
        const float* so = (const float*)(smc + OFF_OUT);
#pragma unroll
        for (int rep = 0; rep < 8; rep++) {
            int idx = rep * 128 + tid;
            int c = idx >> 4, q4 = (idx & 15) * 4;
            float4 v = *(const float4*)(so + c * 68 + q4);
            *(float4*)(out + c * 65536 + bh * 1024 + t0 + q4) = v;
        }
    }
}

// ---------------------------------------------------------------------------
extern "C" void kernel_launch(void* const* d_in, const int* in_sizes, int n_in,
                              void* d_out, int out_size)
{
    const float* qkv  = (const float*)d_in[0];
    const int*   mask = (const int*)  d_in[1];
    const float* emb  = (const float*)d_in[2];
    const float* Wc   = (const float*)d_in[3];
    float* out = (float*)d_out;

    preconv_kernel<<<12288, 256>>>(qkv);
    tok_kernel<<<dim3(9, 6), 256>>>(emb, Wc);
    bmat_kernel<<<dim3(64, 4), 256>>>(qkv, mask);
    cudaFuncSetAttribute(attn_kernel, cudaFuncAttributeMaxDynamicSharedMemorySize, SMEM_DYN);
    attn_kernel<<<dim3(16, 64), 128, SMEM_DYN>>>(qkv, mask, out);
}

// round 9
// speedup vs baseline: 12.9558x; 1.1042x over previous
#include <cuda_runtime.h>
#include <cuda_fp16.h>
#include <cstdint>

// ============================================================================
// out[t] = 0.5*( softmaxN(G+Bn)V + vn + softmaxC(G+Bc; seg==c_t)V + vc )
// G = Q.K^T via mma.sync HMMA fp16. Unnormalized exp2 weights as PV A-frags;
// two fp32 accumulators; counter==2.
// R9: 3 CTAs/SM (128 thr, 64-q tiles, smem 62.9KB, regs<=170), 64-s chunks
// ring-2, fp16 ratio table.
// ============================================================================

#define SCL 0.18033688011112042f   // 0.125 * log2(e)

__device__ float g_tok[9 * 192];
__device__ __half g_Rt[64 * 8 * 1024];  // [bh][c][s] masked exp2(SCL*(Bc-Bn)), fp16
__device__ float g_bn2[64 * 1024];      // [bh][s] = SCL*Bn
// preconverted fp16 tile images (swizzled smem byte-images, pitch-128 tiles)
__device__ __align__(16) unsigned char g_q16[64 * 16 * 8192];   // [bh][qtile 64t]
__device__ __align__(16) unsigned char g_k16[64 * 16 * 8192];   // [bh][ktile 64s]
__device__ __align__(16) unsigned char g_vh [64 * 16 * 8192];   // [bh][vtile 64s]

__device__ __forceinline__ uint32_t smem_u32(const void* p) {
    uint32_t a;
    asm("{ .reg .u64 t; cvta.to.shared.u64 t, %1; cvt.u32.u64 %0, t; }" : "=r"(a) : "l"(p));
    return a;
}
__device__ __forceinline__ float ex2f(float x) {
    float y; asm("ex2.approx.f32 %0, %1;" : "=f"(y) : "f"(x)); return y;
}
__device__ __forceinline__ uint32_t packh2(float lo, float hi) {
    uint32_t r; asm("cvt.rn.f16x2.f32 %0, %1, %2;" : "=r"(r) : "f"(hi), "f"(lo)); return r;
}
// pitch-128 swizzle for 64-wide fp16 tiles: row=ch, byte col = s*2
__device__ __forceinline__ uint32_t SW128(uint32_t row, uint32_t bcol) {
    return row * 128u + (bcol ^ ((row & 7u) << 4));
}
__device__ __forceinline__ void ldsm4t(uint32_t* r, uint32_t addr) {
    asm volatile("ldmatrix.sync.aligned.m8n8.x4.trans.shared.b16 {%0,%1,%2,%3}, [%4];"
        : "=r"(r[0]), "=r"(r[1]), "=r"(r[2]), "=r"(r[3]) : "r"(addr));
}
__device__ __forceinline__ void ldsm4(uint32_t* r, uint32_t addr) {
    asm volatile("ldmatrix.sync.aligned.m8n8.x4.shared.b16 {%0,%1,%2,%3}, [%4];"
        : "=r"(r[0]), "=r"(r[1]), "=r"(r[2]), "=r"(r[3]) : "r"(addr));
}
__device__ __forceinline__ void hmma(float* c, const uint32_t* a, uint32_t b0, uint32_t b1) {
    asm volatile("mma.sync.aligned.m16n8k16.row.col.f32.f16.f16.f32 "
        "{%0,%1,%2,%3},{%4,%5,%6,%7},{%8,%9},{%0,%1,%2,%3};"
        : "+f"(c[0]), "+f"(c[1]), "+f"(c[2]), "+f"(c[3])
        : "r"(a[0]), "r"(a[1]), "r"(a[2]), "r"(a[3]), "r"(b0), "r"(b1));
}
#define CPA_COMMIT() asm volatile("cp.async.commit_group;" ::: "memory")
__device__ __forceinline__ void cpa16(uint32_t dst, const void* src) {
    asm volatile("cp.async.cg.shared.global [%0], [%1], 16;" :: "r"(dst), "l"(src) : "memory");
}
__device__ __forceinline__ void cpa_tile8k(uint32_t dst, const unsigned char* src, int tid) {
#pragma unroll
    for (int rep = 0; rep < 4; rep++) {
        uint32_t o = (uint32_t)(rep * 128 + tid) * 16;
        cpa16(dst + o, src + o);
    }
}

// ---------------- preconvert: qkv f32 -> swizzled fp16 tile images ----------------
__global__ void preconv_kernel(const float* __restrict__ qkv)
{
    int idx = blockIdx.x * 256 + threadIdx.x;          // 64*192*256 total
    int t4 = (idx & 255) * 4;
    int ch = (idx >> 8) % 192;
    int bh = idx / (256 * 192);
    float4 v = *(const float4*)(qkv + (size_t)bh * 196608 + ch * 1024 + t4);
    uint32_t h0 = packh2(v.x, v.y), h1 = packh2(v.z, v.w);
    int tile = t4 >> 6, s = t4 & 63;
    uint32_t off = SW128((uint32_t)(ch & 63), (uint32_t)(s * 2));
    size_t base = ((size_t)bh * 16 + tile) * 8192;
    if (ch < 64)       *(uint2*)(g_q16 + base + off) = make_uint2(h0, h1);
    else if (ch < 128) *(uint2*)(g_k16 + base + off) = make_uint2(h0, h1);
    else               *(uint2*)(g_vh  + base + off) = make_uint2(h0, h1);
}

// ---------------- aux A: class tokens (grid 9 x 6, 4 rows/warp) ----------------
__global__ void tok_kernel(const float* __restrict__ emb, const float* __restrict__ Wc)
{
    __shared__ float e[512];
    int c9 = blockIdx.x;
    for (int k = threadIdx.x; k < 512; k += 256) e[k] = emb[c9 * 512 + k];
    __syncthreads();
    int w = threadIdx.x >> 5, l = threadIdx.x & 31;
#pragma unroll
    for (int rr = 0; rr < 4; rr++) {
        int r = blockIdx.y * 32 + w * 4 + rr;
        const float* wr = Wc + r * 512;
        float acc = 0.f;
#pragma unroll
        for (int k = 0; k < 16; k++) acc = fmaf(wr[l + 32 * k], e[l + 32 * k], acc);
#pragma unroll
        for (int o = 16; o > 0; o >>= 1) acc += __shfl_xor_sync(0xffffffffu, acc, o);
        if (l == 0) g_tok[c9 * 192 + r] = acc;
    }
}

// ---------------- aux B: bn2 + transposed masked exp2 ratio table (fp16) ----------------
__global__ void bmat_kernel(const float* __restrict__ qkv, const int* __restrict__ mask)
{
    __shared__ float tq[9 * 64];
    int bh = blockIdx.x, b = bh >> 3;
    for (int x = threadIdx.x; x < 576; x += 256) tq[x] = g_tok[(x >> 6) * 192 + (x & 63)];
    __syncthreads();
    const float* kb = qkv + bh * 196608 + 65536;
    int s = blockIdx.y * 256 + threadIdx.x;
    float acc[9];
#pragma unroll
    for (int c = 0; c < 9; c++) acc[c] = 0.f;
#pragma unroll 4
    for (int c = 0; c < 64; c++) {
        float kv = kb[c * 1024 + s];
#pragma unroll
        for (int c9 = 0; c9 < 9; c9++) acc[c9] = fmaf(tq[c9 * 64 + c], kv, acc[c9]);
    }
    float bn = acc[8];
    g_bn2[bh * 1024 + s] = SCL * bn;
    int sg = mask[b * 1024 + s];
#pragma unroll
    for (int c = 0; c < 8; c++)
        g_Rt[bh * 8192 + c * 1024 + s] = __float2half((sg == c) ? ex2f(SCL * (acc[c] - bn)) : 0.f);
}

// ---------------- main kernel ----------------
#define OFF_QH    0u
#define OFF_BUF   8192u           /* ring-2: (K 8K + V 8K) x2 = 32KB */
#define OFF_R     40960u          /* Rt fp16 [8][1032] = 16512B */
#define OFF_BN2   57472u          /* 4096B */
#define OFF_TOKV  61568u          /* [9][68] f32 = 2448B */
#define OFF_SEGQ  64016u          /* 256B */
#define OFF_OUT   8192u           /* overlay on ring buffers after mainloop */
#define SMEM_DYN  64384

__global__ void __launch_bounds__(128, 3)
attn_kernel(const float* __restrict__ qkv, const int* __restrict__ mask,
            float* __restrict__ out)
{
    extern __shared__ __align__(16) char smc[];
    const uint32_t sb = smem_u32(smc);

    const int tid = threadIdx.x;
    const int w = tid >> 5, lane = tid & 31;
    const int g = lane >> 2, tg = lane & 3;
    const int bh = blockIdx.y;
    const int qt = blockIdx.x;                 // 0..15 (64-row q tiles)
    const int t0 = qt * 64;
    const int b = bh >> 3;

    const unsigned char* q_g = g_q16 + ((size_t)bh * 16 + qt) * 8192;
    const unsigned char* k_g = g_k16 + ((size_t)bh * 16) * 8192;
    const unsigned char* v_g = g_vh + ((size_t)bh * 16) * 8192;

    // ---- prologue: G0 = Q + Rt + bn2 ; G1 = chunk0 ; G2 = chunk1 ----
    cpa_tile8k(sb + OFF_QH, q_g, tid);
    {
        const unsigned char* Rg = (const unsigned char*)(g_Rt + bh * 8192);
#pragma unroll
        for (int rep = 0; rep < 8; rep++) {
            int idx = rep * 128 + tid;              // 0..1023
            int row = idx >> 7, o16 = idx & 127;    // 128 x 16B = 2048B per row
            cpa16(sb + OFF_R + (uint32_t)row * 2064u + (uint32_t)o16 * 16u,
                  Rg + row * 2048 + o16 * 16);
        }
#pragma unroll
        for (int rep = 0; rep < 2; rep++) {
            uint32_t o = (uint32_t)(rep * 128 + tid) * 16;
            cpa16(sb + OFF_BN2 + o, (const unsigned char*)(g_bn2 + bh * 1024) + o);
        }
    }
    CPA_COMMIT();
    cpa_tile8k(sb + OFF_BUF + 0u,    k_g, tid);
    cpa_tile8k(sb + OFF_BUF + 8192u, v_g, tid);
    CPA_COMMIT();
    cpa_tile8k(sb + OFF_BUF + 16384u, k_g + 8192, tid);
    cpa_tile8k(sb + OFF_BUF + 24576u, v_g + 8192, tid);
    CPA_COMMIT();
    {
        float* tvs = (float*)(smc + OFF_TOKV);
        for (int x = tid; x < 576; x += 128)
            tvs[(x >> 6) * 68 + (x & 63)] = g_tok[(x >> 6) * 192 + 128 + (x & 63)];
        if (tid < 64) ((int*)(smc + OFF_SEGQ))[tid] = mask[b * 1024 + t0 + tid];
    }
    asm volatile("cp.async.wait_group 2;" ::: "memory");   // Q/Rt/bn2 ready
    __syncthreads();

    const int m0w = w * 16;
    const int ci_lo = ((const int*)(smc + OFF_SEGQ))[m0w + g];
    const int ci_hi = ((const int*)(smc + OFF_SEGQ))[m0w + g + 8];
    const uint32_t rb_lo = (uint32_t)ci_lo * 2064u;
    const uint32_t rb_hi = (uint32_t)ci_hi * 2064u;
    const char* Rtc = smc + OFF_R;
    const float* bn2sm = (const float*)(smc + OFF_BN2);

    // ---- persistent Q A-fragments, 4 k-steps ----
    uint32_t qh[4][4];
    {
        int kkA = (lane & 7) + ((lane >> 4) << 3);
        int mmA = m0w + ((lane >> 3) & 1) * 8;
#pragma unroll
        for (int k = 0; k < 4; k++)
            ldsm4t(qh[k], sb + OFF_QH + SW128((uint32_t)(16 * k + kkA), (uint32_t)(mmA * 2)));
    }

    float accN[32], accC[32];
#pragma unroll
    for (int i = 0; i < 32; i++) { accN[i] = 0.f; accC[i] = 0.f; }
    float sNlo = 0.f, sNhi = 0.f, sClo = 0.f, sChi = 0.f;

    const int kkB = lane & 15, nnB8 = (lane >> 4) * 8;
    const int nnV = (lane >> 4) * 8 + (lane & 7), kkV8 = ((lane >> 3) & 1) * 8;

    for (int chk = 0; chk < 16; chk++) {
        if (chk < 15) { asm volatile("cp.async.wait_group 1;" ::: "memory"); }
        else          { asm volatile("cp.async.wait_group 0;" ::: "memory"); }
        __syncthreads();                       // chunk chk visible to all

        const uint32_t bufb = OFF_BUF + (uint32_t)(chk & 1) * 16384u;
        const uint32_t bKH = sb + bufb, bV = sb + bufb + 8192u;
        const int s0 = chk * 64;

#pragma unroll
        for (int ntp = 0; ntp < 4; ntp++) {
            float S[8];
#pragma unroll
            for (int i = 0; i < 8; i++) S[i] = 0.f;
#pragma unroll
            for (int k = 0; k < 4; k++) {
                uint32_t bh4[4];
                ldsm4t(bh4, bKH + SW128((uint32_t)(16 * k + kkB), (uint32_t)((ntp * 16 + nnB8) * 2)));
                hmma(S, qh[k], bh4[0], bh4[1]);
                hmma(S + 4, qh[k], bh4[2], bh4[3]);
            }
            uint32_t aN[4], aC[4];
#pragma unroll
            for (int t = 0; t < 2; t++) {
                const int sA = s0 + ntp * 16 + t * 8 + 2 * tg;
                float2 b2 = *(const float2*)(bn2sm + sA);
                float e0 = ex2f(fmaf(S[4 * t + 0], SCL, b2.x));
                float e1 = ex2f(fmaf(S[4 * t + 1], SCL, b2.y));
                float e2 = ex2f(fmaf(S[4 * t + 2], SCL, b2.x));
                float e3 = ex2f(fmaf(S[4 * t + 3], SCL, b2.y));
                sNlo += e0 + e1; sNhi += e2 + e3;
                aN[2 * t]     = packh2(e0, e1);   // {wlo t0, whi t0, wlo t1, whi t1}
                aN[2 * t + 1] = packh2(e2, e3);
                float2 rl = __half22float2(*(const __half2*)(Rtc + rb_lo + sA * 2));
                float2 rh = __half22float2(*(const __half2*)(Rtc + rb_hi + sA * 2));
                float c0 = e0 * rl.x, c1 = e1 * rl.y;
                float c2 = e2 * rh.x, c3 = e3 * rh.y;
                sClo += c0 + c1; sChi += c2 + c3;
                aC[2 * t]     = packh2(c0, c1);
                aC[2 * t + 1] = packh2(c2, c3);
            }
            // PV for this 16-s group
            const int k0v = ntp * 16;
#pragma unroll
            for (int np = 0; np < 4; np++) {
                uint32_t bv[4];
                ldsm4(bv, bV + SW128((uint32_t)(np * 16 + nnV), (uint32_t)((k0v + kkV8) * 2)));
                hmma(accN + (2 * np) * 4, aN, bv[0], bv[1]);
                hmma(accC + (2 * np) * 4, aC, bv[0], bv[1]);
                hmma(accN + (2 * np + 1) * 4, aN, bv[2], bv[3]);
                hmma(accC + (2 * np + 1) * 4, aC, bv[2], bv[3]);
            }
        }
        __syncthreads();                       // slot chk&1 fully consumed
        if (chk + 2 < 16) {
            const uint32_t nb = OFF_BUF + (uint32_t)(chk & 1) * 16384u;
            cpa_tile8k(sb + nb + 0u,    k_g + (chk + 2) * 8192, tid);
            cpa_tile8k(sb + nb + 8192u, v_g + (chk + 2) * 8192, tid);
            CPA_COMMIT();
        }
    }

    // ---- row-sum reduce across the 4 lanes sharing a row ----
#pragma unroll
    for (int o = 1; o < 4; o <<= 1) {
        sNlo += __shfl_xor_sync(0xffffffffu, sNlo, o);
        sNhi += __shfl_xor_sync(0xffffffffu, sNhi, o);
        sClo += __shfl_xor_sync(0xffffffffu, sClo, o);
        sChi += __shfl_xor_sync(0xffffffffu, sChi, o);
    }
    const float rsNlo = 0.5f / sNlo, rsNhi = 0.5f / sNhi;
    const float rsClo = 0.5f / sClo, rsChi = 0.5f / sChi;

    // ---- stage normalized output to smem [64c][64q] pitch 68 f32 ----
    {
        float* so = (float*)(smc + OFF_OUT);
        const float* tv8 = (const float*)(smc + OFF_TOKV) + 8 * 68;
        const float* tvl = (const float*)(smc + OFF_TOKV) + ci_lo * 68;
        const float* tvh = (const float*)(smc + OFF_TOKV) + ci_hi * 68;
#pragma unroll
        for (int nt = 0; nt < 8; nt++) {
            int c0 = nt * 8 + 2 * tg;
            so[c0 * 68 + m0w + g] =
                accN[nt * 4 + 0] * rsNlo + accC[nt * 4 + 0] * rsClo + 0.5f * (tv8[c0] + tvl[c0]);
            so[(c0 + 1) * 68 + m0w + g] =
                accN[nt * 4 + 1] * rsNlo + accC[nt * 4 + 1] * rsClo + 0.5f * (tv8[c0 + 1] + tvl[c0 + 1]);
            so[c0 * 68 + m0w + g + 8] =
                accN[nt * 4 + 2] * rsNhi + accC[nt * 4 + 2] * rsChi + 0.5f * (tv8[c0] + tvh[c0]);
            so[(c0 + 1) * 68 + m0w + g + 8] =
                accN[nt * 4 + 3] * rsNhi + accC[nt * 4 + 3] * rsChi + 0.5f * (tv8[c0 + 1] + tvh[c0 + 1]);
        }
    }
    __syncthreads();

    // ---- coalesced copy-out: out[c*65536 + bh*1024 + t0 + t] ----
    {
        const float* so = (const float*)(smc + OFF_OUT);
#pragma unroll
        for (int rep = 0; rep < 8; rep++) {
            int idx = rep * 128 + tid;
            int c = idx >> 4, q4 = (idx & 15) * 4;
            float4 v = *(const float4*)(so + c * 68 + q4);
            *(float4*)(out + c * 65536 + bh * 1024 + t0 + q4) = v;
        }
    }
}

// ---------------------------------------------------------------------------
extern "C" void kernel_launch(void* const* d_in, const int* in_sizes, int n_in,
                              void* d_out, int out_size)
{
    const float* qkv  = (const float*)d_in[0];
    const int*   mask = (const int*)  d_in[1];
    const float* emb  = (const float*)d_in[2];
    const float* Wc   = (const float*)d_in[3];
    float* out = (float*)d_out;

    preconv_kernel<<<12288, 256>>>(qkv);
    tok_kernel<<<dim3(9, 6), 256>>>(emb, Wc);
    bmat_kernel<<<dim3(64, 4), 256>>>(qkv, mask);
    cudaFuncSetAttribute(attn_kernel, cudaFuncAttributeMaxDynamicSharedMemorySize, SMEM_DYN);
    attn_kernel<<<dim3(16, 64), 128, SMEM_DYN>>>(qkv, mask, out);
}